// round 12
// baseline (speedup 1.0000x reference)
#include <cuda_runtime.h>
#include <cuda_bf16.h>
#include <float.h>
#include <math.h>

#define A_  64
#define B_  256
#define L_  2000
#define TILE 128
#define NTILE 16
#define NTHR 512

typedef unsigned long long u64;
typedef unsigned int u32;

__device__ float g_U[B_ * L_ * A_];
__device__ float g_pmax[B_ * NTILE * A_];
__device__ float g_psum[B_ * NTILE * A_];
__device__ float g_logZ[B_ * A_];

__device__ float  g_WC[64 * 9];
__device__ float  g_bC[64];
__device__ float2 g_we9[64 * 9];
__device__ float2 g_bep[64];
__device__ float  g_hsb[B_ * 4 * 128];
// bf16 hi/lo weights, [n][k] rows padded to 136 bf16 (272B stride)
__device__ __align__(16) u32 g_w2h[128 * 68], g_w2l[128 * 68];
__device__ __align__(16) u32 g_dfh[64 * 68],  g_dfl[64 * 68];

// ---------------- shared memory layout (bytes, all 16B aligned) -------------
#define SM_BINC  0         // 576
#define SM_BEP   576       // 512
#define SM_L2B   1088      // 512
#define SM_BM    1600      // 256
#define SM_WE9   1856      // 4608
#define SM_AH    6464      // 34816  (h1/h2 hi; later ux[64][129] fp32)
#define SM_AL    41280     // 34816  (lo)
#define SM_W2H   76096     // 34816
#define SM_W2L   110912    // 34816
#define SM_DFH   145728    // 17408
#define SM_DFL   163136    // 17408
#define SM_TOTAL 180544

__device__ __forceinline__ u64 pk2(float x){u64 r;asm("mov.b64 %0,{%1,%1};":"=l"(r):"f"(x));return r;}
__device__ __forceinline__ void fma2(u64&d,u64 a,u64 b){asm("fma.rn.f32x2 %0,%1,%2,%0;":"+l"(d):"l"(a),"l"(b));}
__device__ __forceinline__ float2 up(u64 v){float2 f;asm("mov.b64 {%0,%1},%2;":"=f"(f.x),"=f"(f.y):"l"(v));return f;}
__device__ __forceinline__ u32 pkbf(float x,float y){__nv_bfloat162 t=__floats2bfloat162_rn(x,y);return *(u32*)&t;}
__device__ __forceinline__ void split2(float x,float y,u32&hi,u32&lo){
    hi=pkbf(x,y);
    float fx=__uint_as_float(hi<<16), fy=__uint_as_float(hi&0xffff0000u);
    lo=pkbf(x-fx,y-fy);
}
__device__ __forceinline__ u32 stosh(const void*p){u32 a;asm("{ .reg .u64 t; cvta.to.shared.u64 t,%1; cvt.u32.u64 %0,t; }":"=r"(a):"l"(p));return a;}
__device__ __forceinline__ void ldsm4(u32 addr,u32&r0,u32&r1,u32&r2,u32&r3){
    asm volatile("ldmatrix.sync.aligned.m8n8.x4.shared.b16 {%0,%1,%2,%3},[%4];"
        :"=r"(r0),"=r"(r1),"=r"(r2),"=r"(r3):"r"(addr));
}
__device__ __forceinline__ void mma16816(float* c,u32 a0,u32 a1,u32 a2,u32 a3,u32 b0,u32 b1){
    asm volatile("mma.sync.aligned.m16n8k16.row.col.f32.bf16.bf16.f32 "
        "{%0,%1,%2,%3},{%4,%5,%6,%7},{%8,%9},{%0,%1,%2,%3};"
        :"+f"(c[0]),"+f"(c[1]),"+f"(c[2]),"+f"(c[3])
        :"r"(a0),"r"(a1),"r"(a2),"r"(a3),"r"(b0),"r"(b1));
}

__global__ void init1_kernel(const float* w1, const float* b1, const float* w2, const float* b2)
{
    int t = threadIdx.x;
    if (t < 576) {
        int oc = t / 9, tt = t % 9;
        float s = 0.f;
        for (int ic = 0; ic < 32; ic++) {
            int klo = tt - 4 > 0 ? tt - 4 : 0, khi = tt < 4 ? tt : 4;
            for (int k = klo; k <= khi; k++)
                s += w2[(oc * 32 + ic) * 5 + k] * w1[ic * 5 + (tt - k)];
        }
        g_WC[t] = s;
    } else if (t < 640) {
        int oc = t - 576;
        float s = b2[oc];
        for (int ic = 0; ic < 32; ic++) {
            float ws = 0.f;
            for (int k = 0; k < 5; k++) ws += w2[(oc * 32 + ic) * 5 + k];
            s += b1[ic] * ws;
        }
        g_bC[oc] = s;
    }
}

__global__ void init2_kernel(const float* l1w, const float* l1b,
                             const float* l2w, const float* diff)
{
    int t = blockIdx.x * blockDim.x + threadIdx.x;
    if (t < 576) {
        int jp = t / 9, tt = t % 9;
        float sx = 0.f, sy = 0.f;
        for (int oc = 0; oc < 64; oc++) {
            float wc = g_WC[oc * 9 + tt];
            sx += l1w[(2 * jp) * 64 + oc] * wc;
            sy += l1w[(2 * jp + 1) * 64 + oc] * wc;
        }
        g_we9[t] = make_float2(sx, sy);
    } else if (t < 640) {
        int jp = t - 576;
        float sx = l1b[2 * jp], sy = l1b[2 * jp + 1];
        for (int oc = 0; oc < 64; oc++) {
            float bc = g_bC[oc];
            sx += l1w[(2 * jp) * 64 + oc] * bc;
            sy += l1w[(2 * jp + 1) * 64 + oc] * bc;
        }
        g_bep[jp] = make_float2(sx, sy);
    }
    if (t < 128 * 128) {          // w2[n=j][k]
        int n = t >> 7, k = t & 127;
        float w = l2w[t];
        __nv_bfloat16 hh = __float2bfloat16(w);
        __nv_bfloat16 ll = __float2bfloat16(w - __bfloat162float(hh));
        ((__nv_bfloat16*)g_w2h)[n * 136 + k] = hh;
        ((__nv_bfloat16*)g_w2l)[n * 136 + k] = ll;
    }
    if (t < 64 * 128) {           // diff[n=a][k=j]
        int n = t >> 7, k = t & 127;
        float w = diff[t];
        __nv_bfloat16 hh = __float2bfloat16(w);
        __nv_bfloat16 ll = __float2bfloat16(w - __bfloat162float(hh));
        ((__nv_bfloat16*)g_dfh)[n * 136 + k] = hh;
        ((__nv_bfloat16*)g_dfl)[n * 136 + k] = ll;
    }
}

__global__ void boundary_kernel(const float* binc, const float* w1, const float* b1,
                                const float* w2, const float* b2,
                                const float* l1w, const float* l1b)
{
    __shared__ float c1L[32][4], c1R[32][4], c2b[4][64], xL[8], xR[8];
    int b = blockIdx.x, t = threadIdx.x;
    const float* x = binc + b * L_;
    if (t < 6)            xL[t]     = x[t];
    if (t >= 8 && t < 14) xR[t - 8] = x[L_ - 6 + t - 8];
    __syncthreads();
    {
        int ic = t >> 2, p = t & 3;
        float aL = b1[ic], aR = b1[ic];
        #pragma unroll
        for (int k = 0; k < 5; k++) {
            float w = w1[ic * 5 + k];
            int qL = p + k - 2; if (qL >= 0) aL += w * xL[qL];
            int qR = p + k;     if (qR < 6)  aR += w * xR[qR];
        }
        c1L[ic][p] = aL; c1R[ic][p] = aR;
    }
    __syncthreads();
    {
        int oc = t & 63, li0 = t >> 6;
        #pragma unroll
        for (int e = 0; e < 2; e++) {
            int li = li0 + 2 * e;
            float acc = b2[oc];
            for (int ic = 0; ic < 32; ic++) {
                const float* wr = &w2[(oc * 32 + ic) * 5];
                if (li == 0)      { for (int k = 2; k < 5; k++) acc += wr[k] * c1L[ic][k - 2]; }
                else if (li == 1) { for (int k = 1; k < 5; k++) acc += wr[k] * c1L[ic][k - 1]; }
                else if (li == 2) { for (int k = 0; k < 4; k++) acc += wr[k] * c1R[ic][k]; }
                else              { for (int k = 0; k < 3; k++) acc += wr[k] * c1R[ic][k + 1]; }
            }
            c2b[li][oc] = acc;
        }
    }
    __syncthreads();
    {
        int j = t;
        #pragma unroll
        for (int li = 0; li < 4; li++) {
            float h = l1b[j];
            for (int oc = 0; oc < 64; oc++) h += l1w[j * 64 + oc] * c2b[li][oc];
            g_hsb[b * 512 + li * 128 + j] = fmaxf(h, 0.f);
        }
    }
}

__global__ void __launch_bounds__(NTHR, 1)
fused_kernel(const float* __restrict__ binc_g, const float* __restrict__ l2b_g,
             const float* __restrict__ baseline_g, const int* __restrict__ regions_oi_g)
{
    extern __shared__ char smem[];
    const int t = threadIdx.x, wid = t >> 5, lane = t & 31;
    const int tileIdx = blockIdx.x, b = blockIdx.y;
    const int l0 = tileIdx * TILE;
    const u32 sb = stosh(smem);

    // ---- staging: weights (hi/lo), we9, bep, l2b, bincounts halo ----
    {
        float4* dh = (float4*)(smem + SM_W2H); const float4* shh = (const float4*)g_w2h;
        float4* dl = (float4*)(smem + SM_W2L); const float4* sll = (const float4*)g_w2l;
        for (int i = t; i < 2176; i += NTHR) { dh[i] = shh[i]; dl[i] = sll[i]; }
        float4* eh = (float4*)(smem + SM_DFH); const float4* gh = (const float4*)g_dfh;
        float4* el = (float4*)(smem + SM_DFL); const float4* gl = (const float4*)g_dfl;
        for (int i = t; i < 1088; i += NTHR) { eh[i] = gh[i]; el[i] = gl[i]; }
        float4* d = (float4*)(smem + SM_WE9); const float4* s = (const float4*)g_we9;
        for (int i = t; i < 288; i += NTHR) d[i] = s[i];
    }
    if (t < 32)  ((float4*)(smem + SM_BEP))[t] = ((const float4*)g_bep)[t];
    if (t < 128) ((float*)(smem + SM_L2B))[t]  = l2b_g[t];
    if (t < 136) {
        int l = l0 - 4 + t;
        ((float*)(smem + SM_BINC))[t] = (l >= 0 && l < L_) ? binc_g[b * L_ + l] : 0.f;
    }
    __syncthreads();

    // ---- conv9 -> h1 split into AH/AL bf16 [l][k], 272B row stride ----
    {
        const u64* swe = (const u64*)(smem + SM_WE9);
        const u64* sbep = (const u64*)(smem + SM_BEP);
        const float* sbinc = (const float*)(smem + SM_BINC);
        int jp = t & 63, lbq = t >> 6;     // lbq 0..7
        u64 wp[9];
        #pragma unroll
        for (int k = 0; k < 9; k++) wp[k] = swe[jp * 9 + k];
        u64 bini = sbep[jp];
        #pragma unroll
        for (int q = 0; q < 2; q++) {
            int lb = (lbq + 8 * q) * 8;
            u64 acc[8];
            #pragma unroll
            for (int i = 0; i < 8; i++) acc[i] = bini;
            u64 xv[16];
            #pragma unroll
            for (int g = 0; g < 4; g++) {
                float4 v = *(const float4*)&sbinc[lb + g * 4];
                xv[g*4] = pk2(v.x); xv[g*4+1] = pk2(v.y); xv[g*4+2] = pk2(v.z); xv[g*4+3] = pk2(v.w);
            }
            #pragma unroll
            for (int k = 0; k < 9; k++) {
                u64 w = wp[k];
                #pragma unroll
                for (int i = 0; i < 8; i++) fma2(acc[i], xv[i + k], w);
            }
            #pragma unroll
            for (int i = 0; i < 8; i++) {
                float2 v = up(acc[i]);
                u32 hi, lo; split2(fmaxf(v.x, 0.f), fmaxf(v.y, 0.f), hi, lo);
                u32 ad = (u32)((lb + i) * 272 + jp * 4);
                *(u32*)(smem + SM_AH + ad) = hi;
                *(u32*)(smem + SM_AL + ad) = lo;
            }
        }
    }
    if (tileIdx == 0 || tileIdx == NTILE - 1) {
        __syncthreads();
        if (t < 256) {
            int li = t >> 7, k = t & 127;
            int l  = (tileIdx == 0) ? li : (78 + li);
            int hb = (tileIdx == 0) ? li : (2 + li);
            float v = g_hsb[b * 512 + hb * 128 + k];
            __nv_bfloat16 hh = __float2bfloat16(v);
            __nv_bfloat16 ll = __float2bfloat16(v - __bfloat162float(hh));
            *(__nv_bfloat16*)(smem + SM_AH + l * 272 + k * 2) = hh;
            *(__nv_bfloat16*)(smem + SM_AL + l * 272 + k * 2) = ll;
        }
    }
    __syncthreads();

    // ---- warp tiling: 8 warps along M (16 rows each), 2 along N ----
    const int m0 = (wid & 7) * 16;
    const u32 aoff = (u32)((m0 + (lane & 15)) * 272 + (lane >> 4) * 16);
    const u32 brow = (u32)(((lane >> 4) * 8 + (lane & 7)) * 272 + ((lane >> 3) & 1) * 16);

    // ==== GEMM2: h2 = relu(h1 @ w2^T + b2), M=128 N=128 K=128, 3-term split ====
    {
        const int n0 = (wid >> 3) * 64;
        float C[8][4];
        #pragma unroll
        for (int i = 0; i < 8; i++)
            #pragma unroll
            for (int j = 0; j < 4; j++) C[i][j] = 0.f;
        #pragma unroll 1
        for (int pass = 0; pass < 3; pass++) {
            u32 Ab = sb + (pass == 2 ? SM_AL : SM_AH) + aoff;
            u32 Bb = sb + (pass == 1 ? SM_W2L : SM_W2H) + (u32)(n0 * 272) + brow;
            #pragma unroll 1
            for (int ks = 0; ks < 8; ks++) {
                u32 kb = (u32)(ks * 32);
                u32 a0[4], br[8][2];
                ldsm4(Ab + kb, a0[0], a0[1], a0[2], a0[3]);
                #pragma unroll
                for (int q = 0; q < 4; q++) {
                    u32 r0, r1, r2, r3;
                    ldsm4(Bb + (u32)(q * 16 * 272) + kb, r0, r1, r2, r3);
                    br[2*q][0] = r0; br[2*q][1] = r1; br[2*q+1][0] = r2; br[2*q+1][1] = r3;
                }
                #pragma unroll
                for (int nt = 0; nt < 8; nt++)
                    mma16816(C[nt], a0[0], a0[1], a0[2], a0[3], br[nt][0], br[nt][1]);
            }
        }
        __syncthreads();   // all warps done reading h1 tiles

        // epilogue2: bias+relu, re-split into AH/AL as h2 [l][k=j]
        const float* sl2b = (const float*)(smem + SM_L2B);
        {
            int la = m0 + (lane >> 2);
            int lb2 = la + 8;
            #pragma unroll
            for (int nt = 0; nt < 8; nt++) {
                float* c = C[nt];
                int j = n0 + nt * 8 + (lane & 3) * 2;
                float bj0 = sl2b[j], bj1 = sl2b[j + 1];
                u32 hi, lo;
                split2(fmaxf(c[0] + bj0, 0.f), fmaxf(c[1] + bj1, 0.f), hi, lo);
                *(u32*)(smem + SM_AH + la * 272 + j * 2) = hi;
                *(u32*)(smem + SM_AL + la * 272 + j * 2) = lo;
                split2(fmaxf(c[2] + bj0, 0.f), fmaxf(c[3] + bj1, 0.f), hi, lo);
                *(u32*)(smem + SM_AH + lb2 * 272 + j * 2) = hi;
                *(u32*)(smem + SM_AL + lb2 * 272 + j * 2) = lo;
            }
        }
    }
    __syncthreads();

    // ==== GEMM3: u = h2 @ diff^T + baseline, M=128 N=64 K=128 ====
    float C3[4][4];
    #pragma unroll
    for (int i = 0; i < 4; i++)
        #pragma unroll
        for (int j = 0; j < 4; j++) C3[i][j] = 0.f;
    const int n03 = (wid >> 3) * 32;
    #pragma unroll 1
    for (int pass = 0; pass < 3; pass++) {
        u32 Ab = sb + (pass == 2 ? SM_AL : SM_AH) + aoff;
        u32 Bb = sb + (pass == 1 ? SM_DFL : SM_DFH) + (u32)(n03 * 272) + brow;
        #pragma unroll 1
        for (int ks = 0; ks < 8; ks++) {
            u32 kb = (u32)(ks * 32);
            u32 a0[4], br[4][2];
            ldsm4(Ab + kb, a0[0], a0[1], a0[2], a0[3]);
            #pragma unroll
            for (int q = 0; q < 2; q++) {
                u32 r0, r1, r2, r3;
                ldsm4(Bb + (u32)(q * 16 * 272) + kb, r0, r1, r2, r3);
                br[2*q][0] = r0; br[2*q][1] = r1; br[2*q+1][0] = r2; br[2*q+1][1] = r3;
            }
            #pragma unroll
            for (int nt = 0; nt < 4; nt++)
                mma16816(C3[nt], a0[0], a0[1], a0[2], a0[3], br[nt][0], br[nt][1]);
        }
    }
    __syncthreads();   // all warps done reading h2 -> AH region reusable

    // epilogue3: u = C3 + baseline; write g_U; LSE partials via ux transpose
    {
        const int rgn = regions_oi_g[b];
        float* ux = (float*)(smem + SM_AH);   // [64][129] fp32
        float* bmv = (float*)(smem + SM_BM);
        {
            int lr0 = m0 + (lane >> 2);
            int lr1 = lr0 + 8;
            int gl0 = l0 + lr0, gl1 = l0 + lr1;
            bool v0 = gl0 < L_, v1 = gl1 < L_;
            float base0 = v0 ? baseline_g[rgn * L_ + gl0] : 0.f;
            float base1 = v1 ? baseline_g[rgn * L_ + gl1] : 0.f;
            #pragma unroll
            for (int nt = 0; nt < 4; nt++) {
                float* c = C3[nt];
                int a = n03 + nt * 8 + (lane & 3) * 2;
                float u0 = v0 ? c[0] + base0 : -FLT_MAX;
                float u1 = v0 ? c[1] + base0 : -FLT_MAX;
                float u2 = v1 ? c[2] + base1 : -FLT_MAX;
                float u3 = v1 ? c[3] + base1 : -FLT_MAX;
                if (v0) *(float2*)&g_U[((size_t)(b * L_ + gl0)) * A_ + a] = make_float2(u0, u1);
                if (v1) *(float2*)&g_U[((size_t)(b * L_ + gl1)) * A_ + a] = make_float2(u2, u3);
                ux[a * 129 + lr0] = u0; ux[(a + 1) * 129 + lr0] = u1;
                ux[a * 129 + lr1] = u2; ux[(a + 1) * 129 + lr1] = u3;
            }
        }
        __syncthreads();
        if (t < 64) {
            float m = -FLT_MAX;
            const float* row = &ux[t * 129];
            #pragma unroll 8
            for (int i = 0; i < 128; i++) m = fmaxf(m, row[i]);
            bmv[t] = m;
        }
        __syncthreads();
        {
            int lr0 = m0 + (lane >> 2);
            int lr1 = lr0 + 8;
            #pragma unroll
            for (int nt = 0; nt < 4; nt++) {
                int a = n03 + nt * 8 + (lane & 3) * 2;
                float m0v = bmv[a], m1v = bmv[a + 1];
                ux[a * 129 + lr0]       = __expf(ux[a * 129 + lr0]       - m0v);
                ux[(a + 1) * 129 + lr0] = __expf(ux[(a + 1) * 129 + lr0] - m1v);
                ux[a * 129 + lr1]       = __expf(ux[a * 129 + lr1]       - m0v);
                ux[(a + 1) * 129 + lr1] = __expf(ux[(a + 1) * 129 + lr1] - m1v);
            }
        }
        __syncthreads();
        if (t < 64) {
            float s = 0.f;
            const float* row = &ux[t * 129];
            #pragma unroll 8
            for (int i = 0; i < 128; i++) s += row[i];
            g_pmax[(b * NTILE + tileIdx) * A_ + t] = bmv[t];
            g_psum[(b * NTILE + tileIdx) * A_ + t] = s;
        }
    }
}

__global__ void combine_kernel()
{
    int id = blockIdx.x * blockDim.x + threadIdx.x;
    if (id >= B_ * A_) return;
    int b = id >> 6, a = id & 63;
    float m = -FLT_MAX;
    #pragma unroll
    for (int q = 0; q < NTILE; q++)
        m = fmaxf(m, g_pmax[(b * NTILE + q) * A_ + a]);
    float s = 0.f;
    #pragma unroll
    for (int q = 0; q < NTILE; q++)
        s += g_psum[(b * NTILE + q) * A_ + a] * __expf(g_pmax[(b * NTILE + q) * A_ + a] - m);
    g_logZ[b * A_ + a] = m + logf(s);
}

__global__ void gather_kernel(const int* __restrict__ labels, const int* __restrict__ cell_ix,
                              const int* __restrict__ region_ix, const int* __restrict__ binixs,
                              float* __restrict__ out, int nf)
{
    int f = blockIdx.x * blockDim.x + threadIdx.x;
    if (f >= nf) return;
    int a = labels[cell_ix[f]];
    int b = region_ix[f];
    int l = binixs[f];
    out[f] = g_U[(size_t)(b * L_ + l) * A_ + a] - g_logZ[b * A_ + a] + 5.545177444479562f;
}

extern "C" void kernel_launch(void* const* d_in, const int* in_sizes, int n_in,
                              void* d_out, int out_size)
{
    const float* bincounts  = (const float*)d_in[0];
    const float* conv1_w    = (const float*)d_in[1];
    const float* conv1_b    = (const float*)d_in[2];
    const float* conv2_w    = (const float*)d_in[3];
    const float* conv2_b    = (const float*)d_in[4];
    const float* lin1_w     = (const float*)d_in[5];
    const float* lin1_b     = (const float*)d_in[6];
    const float* lin2_w     = (const float*)d_in[7];
    const float* lin2_b     = (const float*)d_in[8];
    const float* baseline   = (const float*)d_in[9];
    const float* diff       = (const float*)d_in[10];
    const int*   regions_oi = (const int*)d_in[11];
    const int*   labels     = (const int*)d_in[12];
    const int*   cell_ix    = (const int*)d_in[13];
    const int*   region_ix  = (const int*)d_in[14];
    const int*   binixs     = (const int*)d_in[15];
    float* out = (float*)d_out;
    int nf = in_sizes[13];

    cudaFuncSetAttribute(fused_kernel,
                         cudaFuncAttributeMaxDynamicSharedMemorySize, SM_TOTAL);

    init1_kernel<<<1, 640>>>(conv1_w, conv1_b, conv2_w, conv2_b);
    init2_kernel<<<64, 256>>>(lin1_w, lin1_b, lin2_w, diff);
    boundary_kernel<<<B_, 128>>>(bincounts, conv1_w, conv1_b, conv2_w, conv2_b,
                                 lin1_w, lin1_b);

    dim3 grid(NTILE, B_);
    fused_kernel<<<grid, NTHR, SM_TOTAL>>>(bincounts, lin2_b, baseline, regions_oi);
    combine_kernel<<<(B_ * A_ + 255) / 256, 256>>>();
    gather_kernel<<<(nf + 255) / 256, 256>>>(labels, cell_ix, region_ix,
                                             binixs, out, nf);
}

// round 13
// speedup vs baseline: 1.2738x; 1.2738x over previous
#include <cuda_runtime.h>
#include <cuda_fp16.h>
#include <float.h>
#include <math.h>

#define A_  64
#define B_  256
#define L_  2000
#define TILE 128
#define NTILE 16
#define NTHR 512

typedef unsigned long long u64;
typedef unsigned int u32;

__device__ float g_U[B_ * L_ * A_];
__device__ float g_pmax[B_ * NTILE * A_];
__device__ float g_psum[B_ * NTILE * A_];
__device__ float g_logZ[B_ * A_];

__device__ float  g_WC[64 * 9];
__device__ float  g_bC[64];
__device__ float2 g_we9[64 * 9];
__device__ float2 g_bep[64];
__device__ float  g_hsb[B_ * 4 * 128];
// fp16 weights (hi only), [n][k] rows padded to 136 halves (272B stride)
__device__ __align__(16) u32 g_w2h[128 * 68];
__device__ __align__(16) u32 g_dfh[64 * 68];

// ---------------- shared memory layout (bytes, 16B aligned) -----------------
#define SM_BINC  0         // 576
#define SM_BEP   576       // 512
#define SM_L2B   1088      // 512
#define SM_BM    1600      // 256
#define SM_WE9   1856      // 4608
#define SM_AH    6464      // 34816  (h1/h2 hi fp16; later ux[64][129] fp32)
#define SM_AL    41280     // 34816  (lo fp16)
#define SM_W2H   76096     // 34816
#define SM_DFH   110912    // 17408
#define SM_TOTAL 128320

__device__ __forceinline__ u64 pk2(float x){u64 r;asm("mov.b64 %0,{%1,%1};":"=l"(r):"f"(x));return r;}
__device__ __forceinline__ void fma2(u64&d,u64 a,u64 b){asm("fma.rn.f32x2 %0,%1,%2,%0;":"+l"(d):"l"(a),"l"(b));}
__device__ __forceinline__ float2 up(u64 v){float2 f;asm("mov.b64 {%0,%1},%2;":"=f"(f.x),"=f"(f.y):"l"(v));return f;}
// fp16 exact split: x = hi + lo (lo = exact residual rounded to fp16, ~2^-23 loss)
__device__ __forceinline__ void split2h(float x,float y,u32&hi,u32&lo){
    __half hx=__float2half_rn(x), hy=__float2half_rn(y);
    __half2 h2v=__halves2half2(hx,hy); hi=*(u32*)&h2v;
    __half2 l2v=__floats2half2_rn(x-__half2float(hx), y-__half2float(hy));
    lo=*(u32*)&l2v;
}
__device__ __forceinline__ u32 stosh(const void*p){u32 a;asm("{ .reg .u64 t; cvta.to.shared.u64 t,%1; cvt.u32.u64 %0,t; }":"=r"(a):"l"(p));return a;}
__device__ __forceinline__ void ldsm4(u32 addr,u32&r0,u32&r1,u32&r2,u32&r3){
    asm volatile("ldmatrix.sync.aligned.m8n8.x4.shared.b16 {%0,%1,%2,%3},[%4];"
        :"=r"(r0),"=r"(r1),"=r"(r2),"=r"(r3):"r"(addr));
}
__device__ __forceinline__ void mma16816(float* c,u32 a0,u32 a1,u32 a2,u32 a3,u32 b0,u32 b1){
    asm volatile("mma.sync.aligned.m16n8k16.row.col.f32.f16.f16.f32 "
        "{%0,%1,%2,%3},{%4,%5,%6,%7},{%8,%9},{%0,%1,%2,%3};"
        :"+f"(c[0]),"+f"(c[1]),"+f"(c[2]),"+f"(c[3])
        :"r"(a0),"r"(a1),"r"(a2),"r"(a3),"r"(b0),"r"(b1));
}

__global__ void init1_kernel(const float* w1, const float* b1, const float* w2, const float* b2)
{
    int t = threadIdx.x;
    if (t < 576) {
        int oc = t / 9, tt = t % 9;
        float s = 0.f;
        for (int ic = 0; ic < 32; ic++) {
            int klo = tt - 4 > 0 ? tt - 4 : 0, khi = tt < 4 ? tt : 4;
            for (int k = klo; k <= khi; k++)
                s += w2[(oc * 32 + ic) * 5 + k] * w1[ic * 5 + (tt - k)];
        }
        g_WC[t] = s;
    } else if (t < 640) {
        int oc = t - 576;
        float s = b2[oc];
        for (int ic = 0; ic < 32; ic++) {
            float ws = 0.f;
            for (int k = 0; k < 5; k++) ws += w2[(oc * 32 + ic) * 5 + k];
            s += b1[ic] * ws;
        }
        g_bC[oc] = s;
    }
}

__global__ void init2_kernel(const float* l1w, const float* l1b,
                             const float* l2w, const float* diff)
{
    int t = blockIdx.x * blockDim.x + threadIdx.x;
    if (t < 576) {
        int jp = t / 9, tt = t % 9;
        float sx = 0.f, sy = 0.f;
        for (int oc = 0; oc < 64; oc++) {
            float wc = g_WC[oc * 9 + tt];
            sx += l1w[(2 * jp) * 64 + oc] * wc;
            sy += l1w[(2 * jp + 1) * 64 + oc] * wc;
        }
        g_we9[t] = make_float2(sx, sy);
    } else if (t < 640) {
        int jp = t - 576;
        float sx = l1b[2 * jp], sy = l1b[2 * jp + 1];
        for (int oc = 0; oc < 64; oc++) {
            float bc = g_bC[oc];
            sx += l1w[(2 * jp) * 64 + oc] * bc;
            sy += l1w[(2 * jp + 1) * 64 + oc] * bc;
        }
        g_bep[jp] = make_float2(sx, sy);
    }
    if (t < 128 * 128) {          // w2[n=j][k] -> fp16
        int n = t >> 7, k = t & 127;
        ((__half*)g_w2h)[n * 136 + k] = __float2half_rn(l2w[t]);
    }
    if (t < 64 * 128) {           // diff[n=a][k=j] -> fp16
        int n = t >> 7, k = t & 127;
        ((__half*)g_dfh)[n * 136 + k] = __float2half_rn(diff[t]);
    }
}

__global__ void boundary_kernel(const float* binc, const float* w1, const float* b1,
                                const float* w2, const float* b2,
                                const float* l1w, const float* l1b)
{
    __shared__ float c1L[32][4], c1R[32][4], c2b[4][64], xL[8], xR[8];
    int b = blockIdx.x, t = threadIdx.x;
    const float* x = binc + b * L_;
    if (t < 6)            xL[t]     = x[t];
    if (t >= 8 && t < 14) xR[t - 8] = x[L_ - 6 + t - 8];
    __syncthreads();
    {
        int ic = t >> 2, p = t & 3;
        float aL = b1[ic], aR = b1[ic];
        #pragma unroll
        for (int k = 0; k < 5; k++) {
            float w = w1[ic * 5 + k];
            int qL = p + k - 2; if (qL >= 0) aL += w * xL[qL];
            int qR = p + k;     if (qR < 6)  aR += w * xR[qR];
        }
        c1L[ic][p] = aL; c1R[ic][p] = aR;
    }
    __syncthreads();
    {
        int oc = t & 63, li0 = t >> 6;
        #pragma unroll
        for (int e = 0; e < 2; e++) {
            int li = li0 + 2 * e;
            float acc = b2[oc];
            for (int ic = 0; ic < 32; ic++) {
                const float* wr = &w2[(oc * 32 + ic) * 5];
                if (li == 0)      { for (int k = 2; k < 5; k++) acc += wr[k] * c1L[ic][k - 2]; }
                else if (li == 1) { for (int k = 1; k < 5; k++) acc += wr[k] * c1L[ic][k - 1]; }
                else if (li == 2) { for (int k = 0; k < 4; k++) acc += wr[k] * c1R[ic][k]; }
                else              { for (int k = 0; k < 3; k++) acc += wr[k] * c1R[ic][k + 1]; }
            }
            c2b[li][oc] = acc;
        }
    }
    __syncthreads();
    {
        int j = t;
        #pragma unroll
        for (int li = 0; li < 4; li++) {
            float h = l1b[j];
            for (int oc = 0; oc < 64; oc++) h += l1w[j * 64 + oc] * c2b[li][oc];
            g_hsb[b * 512 + li * 128 + j] = fmaxf(h, 0.f);
        }
    }
}

__global__ void __launch_bounds__(NTHR, 1)
fused_kernel(const float* __restrict__ binc_g, const float* __restrict__ l2b_g,
             const float* __restrict__ baseline_g, const int* __restrict__ regions_oi_g)
{
    extern __shared__ char smem[];
    const int t = threadIdx.x, wid = t >> 5, lane = t & 31;
    const int tileIdx = blockIdx.x, b = blockIdx.y;
    const int l0 = tileIdx * TILE;
    const u32 sb = stosh(smem);

    // ---- staging ----
    {
        float4* dh = (float4*)(smem + SM_W2H); const float4* shh = (const float4*)g_w2h;
        for (int i = t; i < 2176; i += NTHR) dh[i] = shh[i];
        float4* eh = (float4*)(smem + SM_DFH); const float4* gh = (const float4*)g_dfh;
        for (int i = t; i < 1088; i += NTHR) eh[i] = gh[i];
        float4* d = (float4*)(smem + SM_WE9); const float4* s = (const float4*)g_we9;
        for (int i = t; i < 288; i += NTHR) d[i] = s[i];
    }
    if (t < 32)  ((float4*)(smem + SM_BEP))[t] = ((const float4*)g_bep)[t];
    if (t < 128) ((float*)(smem + SM_L2B))[t]  = l2b_g[t];
    if (t < 136) {
        int l = l0 - 4 + t;
        ((float*)(smem + SM_BINC))[t] = (l >= 0 && l < L_) ? binc_g[b * L_ + l] : 0.f;
    }
    __syncthreads();

    // ---- conv9 -> h1 split into AH/AL fp16 [l][k], 272B row stride ----
    {
        const u64* swe = (const u64*)(smem + SM_WE9);
        const u64* sbep = (const u64*)(smem + SM_BEP);
        const float* sbinc = (const float*)(smem + SM_BINC);
        int jp = t & 63, lbq = t >> 6;
        u64 wp[9];
        #pragma unroll
        for (int k = 0; k < 9; k++) wp[k] = swe[jp * 9 + k];
        u64 bini = sbep[jp];
        #pragma unroll
        for (int q = 0; q < 2; q++) {
            int lb = (lbq + 8 * q) * 8;
            u64 acc[8];
            #pragma unroll
            for (int i = 0; i < 8; i++) acc[i] = bini;
            u64 xv[16];
            #pragma unroll
            for (int g = 0; g < 4; g++) {
                float4 v = *(const float4*)&sbinc[lb + g * 4];
                xv[g*4] = pk2(v.x); xv[g*4+1] = pk2(v.y); xv[g*4+2] = pk2(v.z); xv[g*4+3] = pk2(v.w);
            }
            #pragma unroll
            for (int k = 0; k < 9; k++) {
                u64 w = wp[k];
                #pragma unroll
                for (int i = 0; i < 8; i++) fma2(acc[i], xv[i + k], w);
            }
            #pragma unroll
            for (int i = 0; i < 8; i++) {
                float2 v = up(acc[i]);
                u32 hi, lo; split2h(fmaxf(v.x, 0.f), fmaxf(v.y, 0.f), hi, lo);
                u32 ad = (u32)((lb + i) * 272 + jp * 4);
                *(u32*)(smem + SM_AH + ad) = hi;
                *(u32*)(smem + SM_AL + ad) = lo;
            }
        }
    }
    if (tileIdx == 0 || tileIdx == NTILE - 1) {
        __syncthreads();
        if (t < 256) {
            int li = t >> 7, k = t & 127;
            int l  = (tileIdx == 0) ? li : (78 + li);
            int hb = (tileIdx == 0) ? li : (2 + li);
            float v = g_hsb[b * 512 + hb * 128 + k];
            __half hh = __float2half_rn(v);
            __half ll = __float2half_rn(v - __half2float(hh));
            *(__half*)(smem + SM_AH + l * 272 + k * 2) = hh;
            *(__half*)(smem + SM_AL + l * 272 + k * 2) = ll;
        }
    }
    __syncthreads();

    // ---- warp tiling: 4 warps along M (32 rows), 4 along N ----
    const int m0 = (wid & 3) * 32;
    const u32 aoff = (u32)((m0 + (lane & 15)) * 272 + (lane >> 4) * 16);
    const u32 brow = (u32)(((lane >> 4) * 8 + (lane & 7)) * 272 + ((lane >> 3) & 1) * 16);

    // ==== GEMM2: h2 = relu(A @ w2h^T + b2), 2-pass (Ah + Al), B loaded once ====
    {
        const int n0 = (wid >> 2) * 32;
        float C[2][4][4];
        #pragma unroll
        for (int mt = 0; mt < 2; mt++)
            #pragma unroll
            for (int nt = 0; nt < 4; nt++)
                #pragma unroll
                for (int j = 0; j < 4; j++) C[mt][nt][j] = 0.f;
        u32 AbH = sb + SM_AH + aoff, AbL = sb + SM_AL + aoff;
        u32 Bb  = sb + SM_W2H + (u32)(n0 * 272) + brow;
        #pragma unroll 1
        for (int ks = 0; ks < 8; ks++) {
            u32 kb = (u32)(ks * 32);
            u32 ah[2][4], al[2][4], bt[4][2];
            ldsm4(AbH + kb,            ah[0][0], ah[0][1], ah[0][2], ah[0][3]);
            ldsm4(AbH + 16 * 272 + kb, ah[1][0], ah[1][1], ah[1][2], ah[1][3]);
            ldsm4(AbL + kb,            al[0][0], al[0][1], al[0][2], al[0][3]);
            ldsm4(AbL + 16 * 272 + kb, al[1][0], al[1][1], al[1][2], al[1][3]);
            #pragma unroll
            for (int q = 0; q < 2; q++) {
                u32 r0, r1, r2, r3;
                ldsm4(Bb + (u32)(q * 16 * 272) + kb, r0, r1, r2, r3);
                bt[2*q][0] = r0; bt[2*q][1] = r1; bt[2*q+1][0] = r2; bt[2*q+1][1] = r3;
            }
            #pragma unroll
            for (int mt = 0; mt < 2; mt++)
                #pragma unroll
                for (int nt = 0; nt < 4; nt++) {
                    mma16816(C[mt][nt], ah[mt][0], ah[mt][1], ah[mt][2], ah[mt][3], bt[nt][0], bt[nt][1]);
                    mma16816(C[mt][nt], al[mt][0], al[mt][1], al[mt][2], al[mt][3], bt[nt][0], bt[nt][1]);
                }
        }
        __syncthreads();   // all warps done reading h1

        // epilogue2: bias+relu, re-split into AH/AL as h2 [l][j]
        const float* sl2b = (const float*)(smem + SM_L2B);
        #pragma unroll
        for (int mt = 0; mt < 2; mt++) {
            int la = m0 + mt * 16 + (lane >> 2);
            int lb2 = la + 8;
            #pragma unroll
            for (int nt = 0; nt < 4; nt++) {
                float* c = C[mt][nt];
                int j = n0 + nt * 8 + (lane & 3) * 2;
                float bj0 = sl2b[j], bj1 = sl2b[j + 1];
                u32 hi, lo;
                split2h(fmaxf(c[0] + bj0, 0.f), fmaxf(c[1] + bj1, 0.f), hi, lo);
                *(u32*)(smem + SM_AH + la * 272 + j * 2) = hi;
                *(u32*)(smem + SM_AL + la * 272 + j * 2) = lo;
                split2h(fmaxf(c[2] + bj0, 0.f), fmaxf(c[3] + bj1, 0.f), hi, lo);
                *(u32*)(smem + SM_AH + lb2 * 272 + j * 2) = hi;
                *(u32*)(smem + SM_AL + lb2 * 272 + j * 2) = lo;
            }
        }
    }
    __syncthreads();

    // ==== GEMM3: u = h2 @ diff^T + baseline, M=128 N=64, 2-pass ====
    float C3[2][2][4];
    #pragma unroll
    for (int mt = 0; mt < 2; mt++)
        #pragma unroll
        for (int nt = 0; nt < 2; nt++)
            #pragma unroll
            for (int j = 0; j < 4; j++) C3[mt][nt][j] = 0.f;
    const int n03 = (wid >> 2) * 16;
    {
        u32 AbH = sb + SM_AH + aoff, AbL = sb + SM_AL + aoff;
        u32 Bb  = sb + SM_DFH + (u32)(n03 * 272) + brow;
        #pragma unroll 1
        for (int ks = 0; ks < 8; ks++) {
            u32 kb = (u32)(ks * 32);
            u32 ah[2][4], al[2][4], bt[2][2];
            ldsm4(AbH + kb,            ah[0][0], ah[0][1], ah[0][2], ah[0][3]);
            ldsm4(AbH + 16 * 272 + kb, ah[1][0], ah[1][1], ah[1][2], ah[1][3]);
            ldsm4(AbL + kb,            al[0][0], al[0][1], al[0][2], al[0][3]);
            ldsm4(AbL + 16 * 272 + kb, al[1][0], al[1][1], al[1][2], al[1][3]);
            {
                u32 r0, r1, r2, r3;
                ldsm4(Bb + kb, r0, r1, r2, r3);
                bt[0][0] = r0; bt[0][1] = r1; bt[1][0] = r2; bt[1][1] = r3;
            }
            #pragma unroll
            for (int mt = 0; mt < 2; mt++)
                #pragma unroll
                for (int nt = 0; nt < 2; nt++) {
                    mma16816(C3[mt][nt], ah[mt][0], ah[mt][1], ah[mt][2], ah[mt][3], bt[nt][0], bt[nt][1]);
                    mma16816(C3[mt][nt], al[mt][0], al[mt][1], al[mt][2], al[mt][3], bt[nt][0], bt[nt][1]);
                }
        }
    }
    __syncthreads();   // done reading h2 -> AH region reusable as ux

    // epilogue3: u = C3 + baseline; write g_U; LSE partials via ux transpose
    {
        const int rgn = regions_oi_g[b];
        float* ux = (float*)(smem + SM_AH);   // [64][129] fp32
        float* bmv = (float*)(smem + SM_BM);
        #pragma unroll
        for (int mt = 0; mt < 2; mt++) {
            int lr0 = m0 + mt * 16 + (lane >> 2);
            int lr1 = lr0 + 8;
            int gl0 = l0 + lr0, gl1 = l0 + lr1;
            bool v0 = gl0 < L_, v1 = gl1 < L_;
            float base0 = v0 ? baseline_g[rgn * L_ + gl0] : 0.f;
            float base1 = v1 ? baseline_g[rgn * L_ + gl1] : 0.f;
            #pragma unroll
            for (int nt = 0; nt < 2; nt++) {
                float* c = C3[mt][nt];
                int a = n03 + nt * 8 + (lane & 3) * 2;
                float u0 = v0 ? c[0] + base0 : -FLT_MAX;
                float u1 = v0 ? c[1] + base0 : -FLT_MAX;
                float u2 = v1 ? c[2] + base1 : -FLT_MAX;
                float u3 = v1 ? c[3] + base1 : -FLT_MAX;
                if (v0) *(float2*)&g_U[((size_t)(b * L_ + gl0)) * A_ + a] = make_float2(u0, u1);
                if (v1) *(float2*)&g_U[((size_t)(b * L_ + gl1)) * A_ + a] = make_float2(u2, u3);
                ux[a * 129 + lr0] = u0; ux[(a + 1) * 129 + lr0] = u1;
                ux[a * 129 + lr1] = u2; ux[(a + 1) * 129 + lr1] = u3;
            }
        }
        __syncthreads();
        // parallel LSE: 8 threads per a-row
        const int row = t >> 3, sub = t & 7;
        const float* rp = &ux[row * 129 + sub * 16];
        float m = -FLT_MAX;
        #pragma unroll
        for (int i = 0; i < 16; i++) m = fmaxf(m, rp[i]);
        #pragma unroll
        for (int off = 4; off > 0; off >>= 1)
            m = fmaxf(m, __shfl_down_sync(0xffffffffu, m, off, 8));
        if (sub == 0) bmv[row] = m;
        __syncthreads();
        for (int idx = t; idx < 64 * 128; idx += NTHR) {
            int a = idx >> 7, l = idx & 127;
            ux[a * 129 + l] = __expf(ux[a * 129 + l] - bmv[a]);
        }
        __syncthreads();
        float s = 0.f;
        #pragma unroll
        for (int i = 0; i < 16; i++) s += rp[i];
        #pragma unroll
        for (int off = 4; off > 0; off >>= 1)
            s += __shfl_down_sync(0xffffffffu, s, off, 8);
        if (sub == 0) {
            g_pmax[(b * NTILE + tileIdx) * A_ + row] = bmv[row];
            g_psum[(b * NTILE + tileIdx) * A_ + row] = s;
        }
    }
}

__global__ void combine_kernel()
{
    int id = blockIdx.x * blockDim.x + threadIdx.x;
    if (id >= B_ * A_) return;
    int b = id >> 6, a = id & 63;
    float m = -FLT_MAX;
    #pragma unroll
    for (int q = 0; q < NTILE; q++)
        m = fmaxf(m, g_pmax[(b * NTILE + q) * A_ + a]);
    float s = 0.f;
    #pragma unroll
    for (int q = 0; q < NTILE; q++)
        s += g_psum[(b * NTILE + q) * A_ + a] * __expf(g_pmax[(b * NTILE + q) * A_ + a] - m);
    g_logZ[b * A_ + a] = m + logf(s);
}

__global__ void gather_kernel(const int* __restrict__ labels, const int* __restrict__ cell_ix,
                              const int* __restrict__ region_ix, const int* __restrict__ binixs,
                              float* __restrict__ out, int nf)
{
    int f = blockIdx.x * blockDim.x + threadIdx.x;
    if (f >= nf) return;
    int a = labels[cell_ix[f]];
    int b = region_ix[f];
    int l = binixs[f];
    out[f] = g_U[(size_t)(b * L_ + l) * A_ + a] - g_logZ[b * A_ + a] + 5.545177444479562f;
}

extern "C" void kernel_launch(void* const* d_in, const int* in_sizes, int n_in,
                              void* d_out, int out_size)
{
    const float* bincounts  = (const float*)d_in[0];
    const float* conv1_w    = (const float*)d_in[1];
    const float* conv1_b    = (const float*)d_in[2];
    const float* conv2_w    = (const float*)d_in[3];
    const float* conv2_b    = (const float*)d_in[4];
    const float* lin1_w     = (const float*)d_in[5];
    const float* lin1_b     = (const float*)d_in[6];
    const float* lin2_w     = (const float*)d_in[7];
    const float* lin2_b     = (const float*)d_in[8];
    const float* baseline   = (const float*)d_in[9];
    const float* diff       = (const float*)d_in[10];
    const int*   regions_oi = (const int*)d_in[11];
    const int*   labels     = (const int*)d_in[12];
    const int*   cell_ix    = (const int*)d_in[13];
    const int*   region_ix  = (const int*)d_in[14];
    const int*   binixs     = (const int*)d_in[15];
    float* out = (float*)d_out;
    int nf = in_sizes[13];

    cudaFuncSetAttribute(fused_kernel,
                         cudaFuncAttributeMaxDynamicSharedMemorySize, SM_TOTAL);

    init1_kernel<<<1, 640>>>(conv1_w, conv1_b, conv2_w, conv2_b);
    init2_kernel<<<64, 256>>>(lin1_w, lin1_b, lin2_w, diff);
    boundary_kernel<<<B_, 128>>>(bincounts, conv1_w, conv1_b, conv2_w, conv2_b,
                                 lin1_w, lin1_b);

    dim3 grid(NTILE, B_);
    fused_kernel<<<grid, NTHR, SM_TOTAL>>>(bincounts, lin2_b, baseline, regions_oi);
    combine_kernel<<<(B_ * A_ + 255) / 256, 256>>>();
    gather_kernel<<<(nf + 255) / 256, 256>>>(labels, cell_ix, region_ix,
                                             binixs, out, nf);
}

// round 15
// speedup vs baseline: 1.5585x; 1.2236x over previous
#include <cuda_runtime.h>
#include <cuda_fp16.h>
#include <float.h>
#include <math.h>

#define A_  64
#define B_  256
#define L_  2000
#define TILE 128
#define NTILE 16
#define NTHR 256

typedef unsigned long long u64;
typedef unsigned int u32;

__device__ float g_U[B_ * L_ * A_];
__device__ float g_pmax[B_ * NTILE * A_];
__device__ float g_psum[B_ * NTILE * A_];
__device__ float g_logZ[B_ * A_];

__device__ float  g_WC[64 * 9];
__device__ float  g_bC[64];
__device__ float2 g_we9[64 * 9];
__device__ float2 g_bep[64];
__device__ float  g_hsb[B_ * 4 * 128];
// fp16 weights (hi only), [n][k] rows padded to 136 halves (272B stride)
__device__ __align__(16) u32 g_w2h[128 * 68];
__device__ __align__(16) u32 g_dfh[64 * 68];

// ---------------- shared memory layout (bytes, 16B aligned) -----------------
#define SM_BINC  0         // 576
#define SM_BEP   576       // 512
#define SM_L2B   1088      // 512
#define SM_BM    1600      // 256
#define SM_WE9   1856      // 4608
#define SM_AH    6464      // 34816 (h1/h2 hi fp16; later ux[64][129] fp32)
#define SM_AL    41280     // 34816 (lo fp16)
#define SM_WB    76096     // 34816 (w2 fp16 during GEMM2; diff fp16 during GEMM3)
#define SM_TOTAL 110912

__device__ __forceinline__ u64 pk2(float x){u64 r;asm("mov.b64 %0,{%1,%1};":"=l"(r):"f"(x));return r;}
__device__ __forceinline__ void fma2(u64&d,u64 a,u64 b){asm("fma.rn.f32x2 %0,%1,%2,%0;":"+l"(d):"l"(a),"l"(b));}
__device__ __forceinline__ float2 up(u64 v){float2 f;asm("mov.b64 {%0,%1},%2;":"=f"(f.x),"=f"(f.y):"l"(v));return f;}
__device__ __forceinline__ void split2h(float x,float y,u32&hi,u32&lo){
    __half hx=__float2half_rn(x), hy=__float2half_rn(y);
    __half2 h2v=__halves2half2(hx,hy); hi=*(u32*)&h2v;
    __half2 l2v=__floats2half2_rn(x-__half2float(hx), y-__half2float(hy));
    lo=*(u32*)&l2v;
}
__device__ __forceinline__ u32 stosh(const void*p){u32 a;asm("{ .reg .u64 t; cvta.to.shared.u64 t,%1; cvt.u32.u64 %0,t; }":"=r"(a):"l"(p));return a;}
__device__ __forceinline__ void ldsm4(u32 addr,u32&r0,u32&r1,u32&r2,u32&r3){
    asm volatile("ldmatrix.sync.aligned.m8n8.x4.shared.b16 {%0,%1,%2,%3},[%4];"
        :"=r"(r0),"=r"(r1),"=r"(r2),"=r"(r3):"r"(addr));
}
__device__ __forceinline__ void mma16816(float* c,u32 a0,u32 a1,u32 a2,u32 a3,u32 b0,u32 b1){
    asm volatile("mma.sync.aligned.m16n8k16.row.col.f32.f16.f16.f32 "
        "{%0,%1,%2,%3},{%4,%5,%6,%7},{%8,%9},{%0,%1,%2,%3};"
        :"+f"(c[0]),"+f"(c[1]),"+f"(c[2]),"+f"(c[3])
        :"r"(a0),"r"(a1),"r"(a2),"r"(a3),"r"(b0),"r"(b1));
}

__global__ void init1_kernel(const float* w1, const float* b1, const float* w2, const float* b2)
{
    int t = threadIdx.x;
    if (t < 576) {
        int oc = t / 9, tt = t % 9;
        float s = 0.f;
        for (int ic = 0; ic < 32; ic++) {
            int klo = tt - 4 > 0 ? tt - 4 : 0, khi = tt < 4 ? tt : 4;
            for (int k = klo; k <= khi; k++)
                s += w2[(oc * 32 + ic) * 5 + k] * w1[ic * 5 + (tt - k)];
        }
        g_WC[t] = s;
    } else if (t < 640) {
        int oc = t - 576;
        float s = b2[oc];
        for (int ic = 0; ic < 32; ic++) {
            float ws = 0.f;
            for (int k = 0; k < 5; k++) ws += w2[(oc * 32 + ic) * 5 + k];
            s += b1[ic] * ws;
        }
        g_bC[oc] = s;
    }
}

__global__ void init2_kernel(const float* l1w, const float* l1b,
                             const float* l2w, const float* diff)
{
    int t = blockIdx.x * blockDim.x + threadIdx.x;
    if (t < 576) {
        int jp = t / 9, tt = t % 9;
        float sx = 0.f, sy = 0.f;
        for (int oc = 0; oc < 64; oc++) {
            float wc = g_WC[oc * 9 + tt];
            sx += l1w[(2 * jp) * 64 + oc] * wc;
            sy += l1w[(2 * jp + 1) * 64 + oc] * wc;
        }
        g_we9[t] = make_float2(sx, sy);
    } else if (t < 640) {
        int jp = t - 576;
        float sx = l1b[2 * jp], sy = l1b[2 * jp + 1];
        for (int oc = 0; oc < 64; oc++) {
            float bc = g_bC[oc];
            sx += l1w[(2 * jp) * 64 + oc] * bc;
            sy += l1w[(2 * jp + 1) * 64 + oc] * bc;
        }
        g_bep[jp] = make_float2(sx, sy);
    }
    if (t < 128 * 128) {
        int n = t >> 7, k = t & 127;
        ((__half*)g_w2h)[n * 136 + k] = __float2half_rn(l2w[t]);
    }
    if (t < 64 * 128) {
        int n = t >> 7, k = t & 127;
        ((__half*)g_dfh)[n * 136 + k] = __float2half_rn(diff[t]);
    }
}

__global__ void boundary_kernel(const float* binc, const float* w1, const float* b1,
                                const float* w2, const float* b2,
                                const float* l1w, const float* l1b)
{
    __shared__ float c1L[32][4], c1R[32][4], c2b[4][64], xL[8], xR[8];
    int b = blockIdx.x, t = threadIdx.x;
    const float* x = binc + b * L_;
    if (t < 6)            xL[t]     = x[t];
    if (t >= 8 && t < 14) xR[t - 8] = x[L_ - 6 + t - 8];
    __syncthreads();
    {
        int ic = t >> 2, p = t & 3;
        float aL = b1[ic], aR = b1[ic];
        #pragma unroll
        for (int k = 0; k < 5; k++) {
            float w = w1[ic * 5 + k];
            int qL = p + k - 2; if (qL >= 0) aL += w * xL[qL];
            int qR = p + k;     if (qR < 6)  aR += w * xR[qR];
        }
        c1L[ic][p] = aL; c1R[ic][p] = aR;
    }
    __syncthreads();
    {
        int oc = t & 63, li0 = t >> 6;
        #pragma unroll
        for (int e = 0; e < 2; e++) {
            int li = li0 + 2 * e;
            float acc = b2[oc];
            for (int ic = 0; ic < 32; ic++) {
                const float* wr = &w2[(oc * 32 + ic) * 5];
                if (li == 0)      { for (int k = 2; k < 5; k++) acc += wr[k] * c1L[ic][k - 2]; }
                else if (li == 1) { for (int k = 1; k < 5; k++) acc += wr[k] * c1L[ic][k - 1]; }
                else if (li == 2) { for (int k = 0; k < 4; k++) acc += wr[k] * c1R[ic][k]; }
                else              { for (int k = 0; k < 3; k++) acc += wr[k] * c1R[ic][k + 1]; }
            }
            c2b[li][oc] = acc;
        }
    }
    __syncthreads();
    {
        int j = t;
        #pragma unroll
        for (int li = 0; li < 4; li++) {
            float h = l1b[j];
            for (int oc = 0; oc < 64; oc++) h += l1w[j * 64 + oc] * c2b[li][oc];
            g_hsb[b * 512 + li * 128 + j] = fmaxf(h, 0.f);
        }
    }
}

__global__ void __launch_bounds__(NTHR, 2)
fused_kernel(const float* __restrict__ binc_g, const float* __restrict__ l2b_g,
             const float* __restrict__ baseline_g, const int* __restrict__ regions_oi_g)
{
    extern __shared__ char smem[];
    const int t = threadIdx.x, wid = t >> 5, lane = t & 31;
    const int tileIdx = blockIdx.x, b = blockIdx.y;
    const int l0 = tileIdx * TILE;
    const u32 sb = stosh(smem);

    // ---- staging: w2 fp16, we9, bep, l2b, bincounts halo ----
    {
        float4* dh = (float4*)(smem + SM_WB); const float4* shh = (const float4*)g_w2h;
        for (int i = t; i < 2176; i += NTHR) dh[i] = shh[i];
        float4* d = (float4*)(smem + SM_WE9); const float4* s = (const float4*)g_we9;
        for (int i = t; i < 288; i += NTHR) d[i] = s[i];
    }
    if (t < 32)  ((float4*)(smem + SM_BEP))[t] = ((const float4*)g_bep)[t];
    if (t < 128) ((float*)(smem + SM_L2B))[t]  = l2b_g[t];
    if (t < 136) {
        int l = l0 - 4 + t;
        ((float*)(smem + SM_BINC))[t] = (l >= 0 && l < L_) ? binc_g[b * L_ + l] : 0.f;
    }
    __syncthreads();

    // ---- conv9 -> h1 split into AH/AL fp16 [l][k], 272B row stride ----
    {
        const u64* swe = (const u64*)(smem + SM_WE9);
        const u64* sbep = (const u64*)(smem + SM_BEP);
        const float* sbinc = (const float*)(smem + SM_BINC);
        int jp = t & 63, lbq = t >> 6;   // lbq 0..3
        u64 wp[9];
        #pragma unroll
        for (int k = 0; k < 9; k++) wp[k] = swe[jp * 9 + k];
        u64 bini = sbep[jp];
        #pragma unroll
        for (int q = 0; q < 4; q++) {
            int lb = (lbq + 4 * q) * 8;
            u64 acc[8];
            #pragma unroll
            for (int i = 0; i < 8; i++) acc[i] = bini;
            u64 xv[16];
            #pragma unroll
            for (int g = 0; g < 4; g++) {
                float4 v = *(const float4*)&sbinc[lb + g * 4];
                xv[g*4] = pk2(v.x); xv[g*4+1] = pk2(v.y); xv[g*4+2] = pk2(v.z); xv[g*4+3] = pk2(v.w);
            }
            #pragma unroll
            for (int k = 0; k < 9; k++) {
                u64 w = wp[k];
                #pragma unroll
                for (int i = 0; i < 8; i++) fma2(acc[i], xv[i + k], w);
            }
            #pragma unroll
            for (int i = 0; i < 8; i++) {
                float2 v = up(acc[i]);
                u32 hi, lo; split2h(fmaxf(v.x, 0.f), fmaxf(v.y, 0.f), hi, lo);
                u32 ad = (u32)((lb + i) * 272 + jp * 4);
                *(u32*)(smem + SM_AH + ad) = hi;
                *(u32*)(smem + SM_AL + ad) = lo;
            }
        }
    }
    if (tileIdx == 0 || tileIdx == NTILE - 1) {
        __syncthreads();
        int li = t >> 7, k = t & 127;
        int l  = (tileIdx == 0) ? li : (78 + li);
        int hb = (tileIdx == 0) ? li : (2 + li);
        float v = g_hsb[b * 512 + hb * 128 + k];
        __half hh = __float2half_rn(v);
        __half ll = __float2half_rn(v - __half2float(hh));
        *(__half*)(smem + SM_AH + l * 272 + k * 2) = hh;
        *(__half*)(smem + SM_AL + l * 272 + k * 2) = ll;
    }
    __syncthreads();

    // ---- warp tiling: 4 warps along M (32 rows), 2 along N ----
    const int m0 = (wid & 3) * 32;
    const u32 aoff = (u32)((m0 + (lane & 15)) * 272 + (lane >> 4) * 16);
    const u32 brow = (u32)(((lane >> 4) * 8 + (lane & 7)) * 272 + ((lane >> 3) & 1) * 16);

    // ==== GEMM2: h2 = relu(A @ w2^T + b2), 2-pass (Ah+Al), B loaded once ====
    {
        const int n0 = (wid >> 2) * 64;
        float C[2][8][4];
        #pragma unroll
        for (int mt = 0; mt < 2; mt++)
            #pragma unroll
            for (int nt = 0; nt < 8; nt++)
                #pragma unroll
                for (int j = 0; j < 4; j++) C[mt][nt][j] = 0.f;
        u32 AbH = sb + SM_AH + aoff, AbL = sb + SM_AL + aoff;
        u32 Bb  = sb + SM_WB + (u32)(n0 * 272) + brow;
        #pragma unroll 1
        for (int ks = 0; ks < 8; ks++) {
            u32 kb = (u32)(ks * 32);
            u32 ah[2][4], al[2][4], bt[8][2];
            ldsm4(AbH + kb,            ah[0][0], ah[0][1], ah[0][2], ah[0][3]);
            ldsm4(AbH + 16 * 272 + kb, ah[1][0], ah[1][1], ah[1][2], ah[1][3]);
            ldsm4(AbL + kb,            al[0][0], al[0][1], al[0][2], al[0][3]);
            ldsm4(AbL + 16 * 272 + kb, al[1][0], al[1][1], al[1][2], al[1][3]);
            #pragma unroll
            for (int q = 0; q < 4; q++) {
                u32 r0, r1, r2, r3;
                ldsm4(Bb + (u32)(q * 16 * 272) + kb, r0, r1, r2, r3);
                bt[2*q][0] = r0; bt[2*q][1] = r1; bt[2*q+1][0] = r2; bt[2*q+1][1] = r3;
            }
            #pragma unroll
            for (int mt = 0; mt < 2; mt++)
                #pragma unroll
                for (int nt = 0; nt < 8; nt++) {
                    mma16816(C[mt][nt], ah[mt][0], ah[mt][1], ah[mt][2], ah[mt][3], bt[nt][0], bt[nt][1]);
                    mma16816(C[mt][nt], al[mt][0], al[mt][1], al[mt][2], al[mt][3], bt[nt][0], bt[nt][1]);
                }
        }
        __syncthreads();   // all warps done reading h1 + w2

        // epilogue2: bias+relu, re-split into AH/AL as h2 [l][j]
        const float* sl2b = (const float*)(smem + SM_L2B);
        #pragma unroll
        for (int mt = 0; mt < 2; mt++) {
            int la = m0 + mt * 16 + (lane >> 2);
            int lb2 = la + 8;
            #pragma unroll
            for (int nt = 0; nt < 8; nt++) {
                float* c = C[mt][nt];
                int j = n0 + nt * 8 + (lane & 3) * 2;
                float bj0 = sl2b[j], bj1 = sl2b[j + 1];
                u32 hi, lo;
                split2h(fmaxf(c[0] + bj0, 0.f), fmaxf(c[1] + bj1, 0.f), hi, lo);
                *(u32*)(smem + SM_AH + la * 272 + j * 2) = hi;
                *(u32*)(smem + SM_AL + la * 272 + j * 2) = lo;
                split2h(fmaxf(c[2] + bj0, 0.f), fmaxf(c[3] + bj1, 0.f), hi, lo);
                *(u32*)(smem + SM_AH + lb2 * 272 + j * 2) = hi;
                *(u32*)(smem + SM_AL + lb2 * 272 + j * 2) = lo;
            }
        }
    }
    {
        float4* eh = (float4*)(smem + SM_WB); const float4* gh = (const float4*)g_dfh;
        for (int i = t; i < 1088; i += NTHR) eh[i] = gh[i];
    }
    __syncthreads();

    // ==== GEMM3: u = h2 @ diff^T + baseline, M=128 N=64, 2-pass ====
    float C3[2][4][4];
    #pragma unroll
    for (int mt = 0; mt < 2; mt++)
        #pragma unroll
        for (int nt = 0; nt < 4; nt++)
            #pragma unroll
            for (int j = 0; j < 4; j++) C3[mt][nt][j] = 0.f;
    const int n03 = (wid >> 2) * 32;
    {
        u32 AbH = sb + SM_AH + aoff, AbL = sb + SM_AL + aoff;
        u32 Bb  = sb + SM_WB + (u32)(n03 * 272) + brow;
        #pragma unroll 1
        for (int ks = 0; ks < 8; ks++) {
            u32 kb = (u32)(ks * 32);
            u32 ah[2][4], al[2][4], bt[4][2];
            ldsm4(AbH + kb,            ah[0][0], ah[0][1], ah[0][2], ah[0][3]);
            ldsm4(AbH + 16 * 272 + kb, ah[1][0], ah[1][1], ah[1][2], ah[1][3]);
            ldsm4(AbL + kb,            al[0][0], al[0][1], al[0][2], al[0][3]);
            ldsm4(AbL + 16 * 272 + kb, al[1][0], al[1][1], al[1][2], al[1][3]);
            #pragma unroll
            for (int q = 0; q < 2; q++) {
                u32 r0, r1, r2, r3;
                ldsm4(Bb + (u32)(q * 16 * 272) + kb, r0, r1, r2, r3);
                bt[2*q][0] = r0; bt[2*q][1] = r1; bt[2*q+1][0] = r2; bt[2*q+1][1] = r3;
            }
            #pragma unroll
            for (int mt = 0; mt < 2; mt++)
                #pragma unroll
                for (int nt = 0; nt < 4; nt++) {
                    mma16816(C3[mt][nt], ah[mt][0], ah[mt][1], ah[mt][2], ah[mt][3], bt[nt][0], bt[nt][1]);
                    mma16816(C3[mt][nt], al[mt][0], al[mt][1], al[mt][2], al[mt][3], bt[nt][0], bt[nt][1]);
                }
        }
    }
    __syncthreads();   // done reading h2 -> AH region reusable as ux

    // epilogue3: u = C3 + baseline; write g_U; LSE partials via ux transpose
    {
        const int rgn = regions_oi_g[b];
        float* ux = (float*)(smem + SM_AH);   // [64][129] fp32
        float* bmv = (float*)(smem + SM_BM);
        #pragma unroll
        for (int mt = 0; mt < 2; mt++) {
            int lr0 = m0 + mt * 16 + (lane >> 2);
            int lr1 = lr0 + 8;
            int gl0 = l0 + lr0, gl1 = l0 + lr1;
            bool v0 = gl0 < L_, v1 = gl1 < L_;
            float base0 = v0 ? baseline_g[rgn * L_ + gl0] : 0.f;
            float base1 = v1 ? baseline_g[rgn * L_ + gl1] : 0.f;
            #pragma unroll
            for (int nt = 0; nt < 4; nt++) {
                float* c = C3[mt][nt];
                int a = n03 + nt * 8 + (lane & 3) * 2;
                float u0 = v0 ? c[0] + base0 : -FLT_MAX;
                float u1 = v0 ? c[1] + base0 : -FLT_MAX;
                float u2 = v1 ? c[2] + base1 : -FLT_MAX;
                float u3 = v1 ? c[3] + base1 : -FLT_MAX;
                if (v0) *(float2*)&g_U[((size_t)(b * L_ + gl0)) * A_ + a] = make_float2(u0, u1);
                if (v1) *(float2*)&g_U[((size_t)(b * L_ + gl1)) * A_ + a] = make_float2(u2, u3);
                ux[a * 129 + lr0] = u0; ux[(a + 1) * 129 + lr0] = u1;
                ux[a * 129 + lr1] = u2; ux[(a + 1) * 129 + lr1] = u3;
            }
        }
        __syncthreads();
        // parallel LSE: 4 threads per a-row, 32 elems each
        const int row = t >> 2, sub = t & 3;
        const float* rp = &ux[row * 129 + sub * 32];
        float m = -FLT_MAX;
        #pragma unroll
        for (int i = 0; i < 32; i++) m = fmaxf(m, rp[i]);
        #pragma unroll
        for (int off = 2; off > 0; off >>= 1)
            m = fmaxf(m, __shfl_down_sync(0xffffffffu, m, off, 4));
        if (sub == 0) bmv[row] = m;
        __syncthreads();
        float mrow = bmv[row];
        float s = 0.f;
        #pragma unroll
        for (int i = 0; i < 32; i++) s += __expf(rp[i] - mrow);
        #pragma unroll
        for (int off = 2; off > 0; off >>= 1)
            s += __shfl_down_sync(0xffffffffu, s, off, 4);
        if (sub == 0) {
            g_pmax[(b * NTILE + tileIdx) * A_ + row] = mrow;
            g_psum[(b * NTILE + tileIdx) * A_ + row] = s;
        }
    }
}

__global__ void combine_kernel()
{
    int id = blockIdx.x * blockDim.x + threadIdx.x;
    if (id >= B_ * A_) return;
    int b = id >> 6, a = id & 63;
    float m = -FLT_MAX;
    #pragma unroll
    for (int q = 0; q < NTILE; q++)
        m = fmaxf(m, g_pmax[(b * NTILE + q) * A_ + a]);
    float s = 0.f;
    #pragma unroll
    for (int q = 0; q < NTILE; q++)
        s += g_psum[(b * NTILE + q) * A_ + a] * __expf(g_pmax[(b * NTILE + q) * A_ + a] - m);
    g_logZ[b * A_ + a] = m + logf(s);
}

__global__ void gather_kernel(const int* __restrict__ labels, const int* __restrict__ cell_ix,
                              const int* __restrict__ region_ix, const int* __restrict__ binixs,
                              float* __restrict__ out, int nf)
{
    int f = blockIdx.x * blockDim.x + threadIdx.x;
    if (f >= nf) return;
    int a = labels[cell_ix[f]];
    int b = region_ix[f];
    int l = binixs[f];
    out[f] = g_U[(size_t)(b * L_ + l) * A_ + a] - g_logZ[b * A_ + a] + 5.545177444479562f;
}

extern "C" void kernel_launch(void* const* d_in, const int* in_sizes, int n_in,
                              void* d_out, int out_size)
{
    const float* bincounts  = (const float*)d_in[0];
    const float* conv1_w    = (const float*)d_in[1];
    const float* conv1_b    = (const float*)d_in[2];
    const float* conv2_w    = (const float*)d_in[3];
    const float* conv2_b    = (const float*)d_in[4];
    const float* lin1_w     = (const float*)d_in[5];
    const float* lin1_b     = (const float*)d_in[6];
    const float* lin2_w     = (const float*)d_in[7];
    const float* lin2_b     = (const float*)d_in[8];
    const float* baseline   = (const float*)d_in[9];
    const float* diff       = (const float*)d_in[10];
    const int*   regions_oi = (const int*)d_in[11];
    const int*   labels     = (const int*)d_in[12];
    const int*   cell_ix    = (const int*)d_in[13];
    const int*   region_ix  = (const int*)d_in[14];
    const int*   binixs     = (const int*)d_in[15];
    float* out = (float*)d_out;
    int nf = in_sizes[13];

    cudaFuncSetAttribute(fused_kernel,
                         cudaFuncAttributeMaxDynamicSharedMemorySize, SM_TOTAL);

    init1_kernel<<<1, 640>>>(conv1_w, conv1_b, conv2_w, conv2_b);
    init2_kernel<<<64, 256>>>(lin1_w, lin1_b, lin2_w, diff);
    boundary_kernel<<<B_, 128>>>(bincounts, conv1_w, conv1_b, conv2_w, conv2_b,
                                 lin1_w, lin1_b);

    dim3 grid(NTILE, B_);
    fused_kernel<<<grid, NTHR, SM_TOTAL>>>(bincounts, lin2_b, baseline, regions_oi);
    combine_kernel<<<(B_ * A_ + 255) / 256, 256>>>();
    gather_kernel<<<(nf + 255) / 256, 256>>>(labels, cell_ix, region_ix,
                                             binixs, out, nf);
}

// round 16
// speedup vs baseline: 1.6961x; 1.0883x over previous
#include <cuda_runtime.h>
#include <cuda_fp16.h>
#include <float.h>
#include <math.h>

#define A_  64
#define B_  256
#define L_  2000
#define TILE 128
#define NTILE 16
#define NTHR 256

typedef unsigned long long u64;
typedef unsigned int u32;

__device__ float g_U[B_ * L_ * A_];
__device__ float g_pmax[B_ * NTILE * A_];
__device__ float g_psum[B_ * NTILE * A_];
__device__ float g_logZ[B_ * A_];

__device__ float2 g_we9[64 * 9];
__device__ float2 g_bep[64];
__device__ float  g_hsb[B_ * 4 * 128];
// fp16 weights, [n][k] rows padded to 136 halves (272B stride)
__device__ __align__(16) u32 g_w2h[128 * 68];
__device__ __align__(16) u32 g_dfh[64 * 68];

// ---------------- shared memory layout (bytes, 16B aligned) -----------------
#define SM_BINC  0         // 576
#define SM_BEP   576       // 512
#define SM_L2B   1088      // 512
#define SM_BM    1600      // 256
#define SM_WE9   1856      // 4608
#define SM_AH    6464      // 34816 (h1/h2 hi fp16; later ux[64][129] fp32)
#define SM_AL    41280     // 34816 (lo fp16)
#define SM_WB    76096     // 34816 (w2 fp16 during GEMM2; diff fp16 during GEMM3)
#define SM_TOTAL 110912

__device__ __forceinline__ u64 pk2(float x){u64 r;asm("mov.b64 %0,{%1,%1};":"=l"(r):"f"(x));return r;}
__device__ __forceinline__ void fma2(u64&d,u64 a,u64 b){asm("fma.rn.f32x2 %0,%1,%2,%0;":"+l"(d):"l"(a),"l"(b));}
__device__ __forceinline__ float2 up(u64 v){float2 f;asm("mov.b64 {%0,%1},%2;":"=f"(f.x),"=f"(f.y):"l"(v));return f;}
__device__ __forceinline__ void split2h(float x,float y,u32&hi,u32&lo){
    __half hx=__float2half_rn(x), hy=__float2half_rn(y);
    __half2 h2v=__halves2half2(hx,hy); hi=*(u32*)&h2v;
    __half2 l2v=__floats2half2_rn(x-__half2float(hx), y-__half2float(hy));
    lo=*(u32*)&l2v;
}
__device__ __forceinline__ u32 stosh(const void*p){u32 a;asm("{ .reg .u64 t; cvta.to.shared.u64 t,%1; cvt.u32.u64 %0,t; }":"=r"(a):"l"(p));return a;}
__device__ __forceinline__ void ldsm4(u32 addr,u32&r0,u32&r1,u32&r2,u32&r3){
    asm volatile("ldmatrix.sync.aligned.m8n8.x4.shared.b16 {%0,%1,%2,%3},[%4];"
        :"=r"(r0),"=r"(r1),"=r"(r2),"=r"(r3):"r"(addr));
}
__device__ __forceinline__ void mma16816(float* c,u32 a0,u32 a1,u32 a2,u32 a3,u32 b0,u32 b1){
    asm volatile("mma.sync.aligned.m16n8k16.row.col.f32.f16.f16.f32 "
        "{%0,%1,%2,%3},{%4,%5,%6,%7},{%8,%9},{%0,%1,%2,%3};"
        :"+f"(c[0]),"+f"(c[1]),"+f"(c[2]),"+f"(c[3])
        :"r"(a0),"r"(a1),"r"(a2),"r"(a3),"r"(b0),"r"(b1));
}

// ===== ONE prep kernel: boundary (blocks 0..255), we9/bep (block 256),
// ===== fp16 weight transposes (blocks 257..288), 128 threads each ==========
__global__ void prep_kernel(const float* __restrict__ binc,
                            const float* __restrict__ w1, const float* __restrict__ b1,
                            const float* __restrict__ w2, const float* __restrict__ b2,
                            const float* __restrict__ l1w, const float* __restrict__ l1b,
                            const float* __restrict__ l2w, const float* __restrict__ diff)
{
    const int blk = blockIdx.x, t = threadIdx.x;

    if (blk < 256) {
        // ---- boundary: exact h1 at l = 0,1,L-2,L-1 for b = blk ----
        __shared__ float c1L[32][4], c1R[32][4], c2b[4][64], xL[8], xR[8];
        int b = blk;
        const float* x = binc + b * L_;
        if (t < 6)            xL[t]     = x[t];
        if (t >= 8 && t < 14) xR[t - 8] = x[L_ - 6 + t - 8];
        __syncthreads();
        {
            int ic = t >> 2, p = t & 3;
            float aL = b1[ic], aR = b1[ic];
            #pragma unroll
            for (int k = 0; k < 5; k++) {
                float w = w1[ic * 5 + k];
                int qL = p + k - 2; if (qL >= 0) aL += w * xL[qL];
                int qR = p + k;     if (qR < 6)  aR += w * xR[qR];
            }
            c1L[ic][p] = aL; c1R[ic][p] = aR;
        }
        __syncthreads();
        {
            int oc = t & 63, li0 = t >> 6;
            #pragma unroll
            for (int e = 0; e < 2; e++) {
                int li = li0 + 2 * e;
                float acc = b2[oc];
                for (int ic = 0; ic < 32; ic++) {
                    const float* wr = &w2[(oc * 32 + ic) * 5];
                    if (li == 0)      { for (int k = 2; k < 5; k++) acc += wr[k] * c1L[ic][k - 2]; }
                    else if (li == 1) { for (int k = 1; k < 5; k++) acc += wr[k] * c1L[ic][k - 1]; }
                    else if (li == 2) { for (int k = 0; k < 4; k++) acc += wr[k] * c1R[ic][k]; }
                    else              { for (int k = 0; k < 3; k++) acc += wr[k] * c1R[ic][k + 1]; }
                }
                c2b[li][oc] = acc;
            }
        }
        __syncthreads();
        {
            int j = t;
            #pragma unroll
            for (int li = 0; li < 4; li++) {
                float h = l1b[j];
                for (int oc = 0; oc < 64; oc++) h += l1w[j * 64 + oc] * c2b[li][oc];
                g_hsb[b * 512 + li * 128 + j] = fmaxf(h, 0.f);
            }
        }
    } else if (blk == 256) {
        // ---- WC/bC in smem, then fold lin1 -> we9/bep ----
        __shared__ float sWC[64 * 9], sbC[64];
        for (int i = t; i < 576; i += 128) {
            int oc = i / 9, tt = i % 9;
            float s = 0.f;
            for (int ic = 0; ic < 32; ic++) {
                int klo = tt - 4 > 0 ? tt - 4 : 0, khi = tt < 4 ? tt : 4;
                for (int k = klo; k <= khi; k++)
                    s += w2[(oc * 32 + ic) * 5 + k] * w1[ic * 5 + (tt - k)];
            }
            sWC[i] = s;
        }
        if (t < 64) {
            float s = b2[t];
            for (int ic = 0; ic < 32; ic++) {
                float ws = 0.f;
                for (int k = 0; k < 5; k++) ws += w2[(t * 32 + ic) * 5 + k];
                s += b1[ic] * ws;
            }
            sbC[t] = s;
        }
        __syncthreads();
        for (int i = t; i < 576; i += 128) {
            int jp = i / 9, tt = i % 9;
            float sx = 0.f, sy = 0.f;
            for (int oc = 0; oc < 64; oc++) {
                float wc = sWC[oc * 9 + tt];
                sx += l1w[(2 * jp) * 64 + oc] * wc;
                sy += l1w[(2 * jp + 1) * 64 + oc] * wc;
            }
            g_we9[i] = make_float2(sx, sy);
        }
        if (t < 64) {
            int jp = t;
            float sx = l1b[2 * jp], sy = l1b[2 * jp + 1];
            for (int oc = 0; oc < 64; oc++) {
                float bc = sbC[oc];
                sx += l1w[(2 * jp) * 64 + oc] * bc;
                sy += l1w[(2 * jp + 1) * 64 + oc] * bc;
            }
            g_bep[jp] = make_float2(sx, sy);
        }
    } else {
        // ---- fp16 weight transposes, grid-stride over 32 blocks ----
        int base = (blk - 257) * 128 + t;
        for (int i = base; i < 128 * 128; i += 32 * 128) {
            int n = i >> 7, k = i & 127;
            ((__half*)g_w2h)[n * 136 + k] = __float2half_rn(l2w[i]);
        }
        for (int i = base; i < 64 * 128; i += 32 * 128) {
            int n = i >> 7, k = i & 127;
            ((__half*)g_dfh)[n * 136 + k] = __float2half_rn(diff[i]);
        }
    }
}

__global__ void __launch_bounds__(NTHR, 2)
fused_kernel(const float* __restrict__ binc_g, const float* __restrict__ l2b_g,
             const float* __restrict__ baseline_g, const int* __restrict__ regions_oi_g)
{
    extern __shared__ char smem[];
    const int t = threadIdx.x, wid = t >> 5, lane = t & 31;
    const int tileIdx = blockIdx.x, b = blockIdx.y;
    const int l0 = tileIdx * TILE;
    const u32 sb = stosh(smem);

    // ---- staging: w2 fp16, we9, bep, l2b, bincounts halo ----
    {
        float4* dh = (float4*)(smem + SM_WB); const float4* shh = (const float4*)g_w2h;
        for (int i = t; i < 2176; i += NTHR) dh[i] = shh[i];
        float4* d = (float4*)(smem + SM_WE9); const float4* s = (const float4*)g_we9;
        for (int i = t; i < 288; i += NTHR) d[i] = s[i];
    }
    if (t < 32)  ((float4*)(smem + SM_BEP))[t] = ((const float4*)g_bep)[t];
    if (t < 128) ((float*)(smem + SM_L2B))[t]  = l2b_g[t];
    if (t < 136) {
        int l = l0 - 4 + t;
        ((float*)(smem + SM_BINC))[t] = (l >= 0 && l < L_) ? binc_g[b * L_ + l] : 0.f;
    }
    __syncthreads();

    // ---- conv9 -> h1 split into AH/AL fp16 [l][k], 272B row stride ----
    {
        const u64* swe = (const u64*)(smem + SM_WE9);
        const u64* sbep = (const u64*)(smem + SM_BEP);
        const float* sbinc = (const float*)(smem + SM_BINC);
        int jp = t & 63, lbq = t >> 6;   // lbq 0..3
        u64 wp[9];
        #pragma unroll
        for (int k = 0; k < 9; k++) wp[k] = swe[jp * 9 + k];
        u64 bini = sbep[jp];
        #pragma unroll
        for (int q = 0; q < 4; q++) {
            int lb = (lbq + 4 * q) * 8;
            u64 acc[8];
            #pragma unroll
            for (int i = 0; i < 8; i++) acc[i] = bini;
            u64 xv[16];
            #pragma unroll
            for (int g = 0; g < 4; g++) {
                float4 v = *(const float4*)&sbinc[lb + g * 4];
                xv[g*4] = pk2(v.x); xv[g*4+1] = pk2(v.y); xv[g*4+2] = pk2(v.z); xv[g*4+3] = pk2(v.w);
            }
            #pragma unroll
            for (int k = 0; k < 9; k++) {
                u64 w = wp[k];
                #pragma unroll
                for (int i = 0; i < 8; i++) fma2(acc[i], xv[i + k], w);
            }
            #pragma unroll
            for (int i = 0; i < 8; i++) {
                float2 v = up(acc[i]);
                u32 hi, lo; split2h(fmaxf(v.x, 0.f), fmaxf(v.y, 0.f), hi, lo);
                u32 ad = (u32)((lb + i) * 272 + jp * 4);
                *(u32*)(smem + SM_AH + ad) = hi;
                *(u32*)(smem + SM_AL + ad) = lo;
            }
        }
    }
    if (tileIdx == 0 || tileIdx == NTILE - 1) {
        __syncthreads();
        int li = t >> 7, k = t & 127;
        int l  = (tileIdx == 0) ? li : (78 + li);
        int hb = (tileIdx == 0) ? li : (2 + li);
        float v = g_hsb[b * 512 + hb * 128 + k];
        __half hh = __float2half_rn(v);
        __half ll = __float2half_rn(v - __half2float(hh));
        *(__half*)(smem + SM_AH + l * 272 + k * 2) = hh;
        *(__half*)(smem + SM_AL + l * 272 + k * 2) = ll;
    }
    __syncthreads();

    // ---- warp tiling: 4 warps along M (32 rows), 2 along N ----
    const int m0 = (wid & 3) * 32;
    const u32 aoff = (u32)((m0 + (lane & 15)) * 272 + (lane >> 4) * 16);
    const u32 brow = (u32)(((lane >> 4) * 8 + (lane & 7)) * 272 + ((lane >> 3) & 1) * 16);

    // ==== GEMM2: h2 = relu(A @ w2^T + b2), 2-pass (Ah+Al), B loaded once ====
    {
        const int n0 = (wid >> 2) * 64;
        float C[2][8][4];
        #pragma unroll
        for (int mt = 0; mt < 2; mt++)
            #pragma unroll
            for (int nt = 0; nt < 8; nt++)
                #pragma unroll
                for (int j = 0; j < 4; j++) C[mt][nt][j] = 0.f;
        u32 AbH = sb + SM_AH + aoff, AbL = sb + SM_AL + aoff;
        u32 Bb  = sb + SM_WB + (u32)(n0 * 272) + brow;
        #pragma unroll 2
        for (int ks = 0; ks < 8; ks++) {
            u32 kb = (u32)(ks * 32);
            u32 ah[2][4], al[2][4], bt[8][2];
            ldsm4(AbH + kb,            ah[0][0], ah[0][1], ah[0][2], ah[0][3]);
            ldsm4(AbH + 16 * 272 + kb, ah[1][0], ah[1][1], ah[1][2], ah[1][3]);
            ldsm4(AbL + kb,            al[0][0], al[0][1], al[0][2], al[0][3]);
            ldsm4(AbL + 16 * 272 + kb, al[1][0], al[1][1], al[1][2], al[1][3]);
            #pragma unroll
            for (int q = 0; q < 4; q++) {
                u32 r0, r1, r2, r3;
                ldsm4(Bb + (u32)(q * 16 * 272) + kb, r0, r1, r2, r3);
                bt[2*q][0] = r0; bt[2*q][1] = r1; bt[2*q+1][0] = r2; bt[2*q+1][1] = r3;
            }
            #pragma unroll
            for (int mt = 0; mt < 2; mt++)
                #pragma unroll
                for (int nt = 0; nt < 8; nt++) {
                    mma16816(C[mt][nt], ah[mt][0], ah[mt][1], ah[mt][2], ah[mt][3], bt[nt][0], bt[nt][1]);
                    mma16816(C[mt][nt], al[mt][0], al[mt][1], al[mt][2], al[mt][3], bt[nt][0], bt[nt][1]);
                }
        }
        __syncthreads();   // all warps done reading h1 + w2

        // epilogue2: bias+relu, re-split into AH/AL as h2 [l][j]
        const float* sl2b = (const float*)(smem + SM_L2B);
        #pragma unroll
        for (int mt = 0; mt < 2; mt++) {
            int la = m0 + mt * 16 + (lane >> 2);
            int lb2 = la + 8;
            #pragma unroll
            for (int nt = 0; nt < 8; nt++) {
                float* c = C[mt][nt];
                int j = n0 + nt * 8 + (lane & 3) * 2;
                float bj0 = sl2b[j], bj1 = sl2b[j + 1];
                u32 hi, lo;
                split2h(fmaxf(c[0] + bj0, 0.f), fmaxf(c[1] + bj1, 0.f), hi, lo);
                *(u32*)(smem + SM_AH + la * 272 + j * 2) = hi;
                *(u32*)(smem + SM_AL + la * 272 + j * 2) = lo;
                split2h(fmaxf(c[2] + bj0, 0.f), fmaxf(c[3] + bj1, 0.f), hi, lo);
                *(u32*)(smem + SM_AH + lb2 * 272 + j * 2) = hi;
                *(u32*)(smem + SM_AL + lb2 * 272 + j * 2) = lo;
            }
        }
    }
    {
        float4* eh = (float4*)(smem + SM_WB); const float4* gh = (const float4*)g_dfh;
        for (int i = t; i < 1088; i += NTHR) eh[i] = gh[i];
    }
    __syncthreads();

    // ==== GEMM3: u = h2 @ diff^T + baseline, M=128 N=64, 2-pass ====
    float C3[2][4][4];
    #pragma unroll
    for (int mt = 0; mt < 2; mt++)
        #pragma unroll
        for (int nt = 0; nt < 4; nt++)
            #pragma unroll
            for (int j = 0; j < 4; j++) C3[mt][nt][j] = 0.f;
    const int n03 = (wid >> 2) * 32;
    {
        u32 AbH = sb + SM_AH + aoff, AbL = sb + SM_AL + aoff;
        u32 Bb  = sb + SM_WB + (u32)(n03 * 272) + brow;
        #pragma unroll 2
        for (int ks = 0; ks < 8; ks++) {
            u32 kb = (u32)(ks * 32);
            u32 ah[2][4], al[2][4], bt[4][2];
            ldsm4(AbH + kb,            ah[0][0], ah[0][1], ah[0][2], ah[0][3]);
            ldsm4(AbH + 16 * 272 + kb, ah[1][0], ah[1][1], ah[1][2], ah[1][3]);
            ldsm4(AbL + kb,            al[0][0], al[0][1], al[0][2], al[0][3]);
            ldsm4(AbL + 16 * 272 + kb, al[1][0], al[1][1], al[1][2], al[1][3]);
            #pragma unroll
            for (int q = 0; q < 2; q++) {
                u32 r0, r1, r2, r3;
                ldsm4(Bb + (u32)(q * 16 * 272) + kb, r0, r1, r2, r3);
                bt[2*q][0] = r0; bt[2*q][1] = r1; bt[2*q+1][0] = r2; bt[2*q+1][1] = r3;
            }
            #pragma unroll
            for (int mt = 0; mt < 2; mt++)
                #pragma unroll
                for (int nt = 0; nt < 4; nt++) {
                    mma16816(C3[mt][nt], ah[mt][0], ah[mt][1], ah[mt][2], ah[mt][3], bt[nt][0], bt[nt][1]);
                    mma16816(C3[mt][nt], al[mt][0], al[mt][1], al[mt][2], al[mt][3], bt[nt][0], bt[nt][1]);
                }
        }
    }
    __syncthreads();   // done reading h2 -> AH region reusable as ux

    // epilogue3: u = C3 + baseline; write g_U; LSE partials via ux transpose
    {
        const int rgn = regions_oi_g[b];
        float* ux = (float*)(smem + SM_AH);   // [64][129] fp32
        float* bmv = (float*)(smem + SM_BM);
        #pragma unroll
        for (int mt = 0; mt < 2; mt++) {
            int lr0 = m0 + mt * 16 + (lane >> 2);
            int lr1 = lr0 + 8;
            int gl0 = l0 + lr0, gl1 = l0 + lr1;
            bool v0 = gl0 < L_, v1 = gl1 < L_;
            float base0 = v0 ? baseline_g[rgn * L_ + gl0] : 0.f;
            float base1 = v1 ? baseline_g[rgn * L_ + gl1] : 0.f;
            #pragma unroll
            for (int nt = 0; nt < 4; nt++) {
                float* c = C3[mt][nt];
                int a = n03 + nt * 8 + (lane & 3) * 2;
                float u0 = v0 ? c[0] + base0 : -FLT_MAX;
                float u1 = v0 ? c[1] + base0 : -FLT_MAX;
                float u2 = v1 ? c[2] + base1 : -FLT_MAX;
                float u3 = v1 ? c[3] + base1 : -FLT_MAX;
                if (v0) *(float2*)&g_U[((size_t)(b * L_ + gl0)) * A_ + a] = make_float2(u0, u1);
                if (v1) *(float2*)&g_U[((size_t)(b * L_ + gl1)) * A_ + a] = make_float2(u2, u3);
                ux[a * 129 + lr0] = u0; ux[(a + 1) * 129 + lr0] = u1;
                ux[a * 129 + lr1] = u2; ux[(a + 1) * 129 + lr1] = u3;
            }
        }
        __syncthreads();
        // parallel LSE: 4 threads per a-row, 32 elems each
        const int row = t >> 2, sub = t & 3;
        const float* rp = &ux[row * 129 + sub * 32];
        float m = -FLT_MAX;
        #pragma unroll
        for (int i = 0; i < 32; i++) m = fmaxf(m, rp[i]);
        #pragma unroll
        for (int off = 2; off > 0; off >>= 1)
            m = fmaxf(m, __shfl_down_sync(0xffffffffu, m, off, 4));
        if (sub == 0) bmv[row] = m;
        __syncthreads();
        float mrow = bmv[row];
        float s = 0.f;
        #pragma unroll
        for (int i = 0; i < 32; i++) s += __expf(rp[i] - mrow);
        #pragma unroll
        for (int off = 2; off > 0; off >>= 1)
            s += __shfl_down_sync(0xffffffffu, s, off, 4);
        if (sub == 0) {
            g_pmax[(b * NTILE + tileIdx) * A_ + row] = mrow;
            g_psum[(b * NTILE + tileIdx) * A_ + row] = s;
        }
    }
}

__global__ void combine_kernel()
{
    int id = blockIdx.x * blockDim.x + threadIdx.x;
    if (id >= B_ * A_) return;
    int b = id >> 6, a = id & 63;
    float m = -FLT_MAX;
    #pragma unroll
    for (int q = 0; q < NTILE; q++)
        m = fmaxf(m, g_pmax[(b * NTILE + q) * A_ + a]);
    float s = 0.f;
    #pragma unroll
    for (int q = 0; q < NTILE; q++)
        s += g_psum[(b * NTILE + q) * A_ + a] * __expf(g_pmax[(b * NTILE + q) * A_ + a] - m);
    g_logZ[b * A_ + a] = m + logf(s);
}

__global__ void gather_kernel(const int* __restrict__ labels, const int* __restrict__ cell_ix,
                              const int* __restrict__ region_ix, const int* __restrict__ binixs,
                              float* __restrict__ out, int nf)
{
    int f = blockIdx.x * blockDim.x + threadIdx.x;
    if (f >= nf) return;
    int a = labels[cell_ix[f]];
    int b = region_ix[f];
    int l = binixs[f];
    out[f] = g_U[(size_t)(b * L_ + l) * A_ + a] - g_logZ[b * A_ + a] + 5.545177444479562f;
}

extern "C" void kernel_launch(void* const* d_in, const int* in_sizes, int n_in,
                              void* d_out, int out_size)
{
    const float* bincounts  = (const float*)d_in[0];
    const float* conv1_w    = (const float*)d_in[1];
    const float* conv1_b    = (const float*)d_in[2];
    const float* conv2_w    = (const float*)d_in[3];
    const float* conv2_b    = (const float*)d_in[4];
    const float* lin1_w     = (const float*)d_in[5];
    const float* lin1_b     = (const float*)d_in[6];
    const float* lin2_w     = (const float*)d_in[7];
    const float* lin2_b     = (const float*)d_in[8];
    const float* baseline   = (const float*)d_in[9];
    const float* diff       = (const float*)d_in[10];
    const int*   regions_oi = (const int*)d_in[11];
    const int*   labels     = (const int*)d_in[12];
    const int*   cell_ix    = (const int*)d_in[13];
    const int*   region_ix  = (const int*)d_in[14];
    const int*   binixs     = (const int*)d_in[15];
    float* out = (float*)d_out;
    int nf = in_sizes[13];

    cudaFuncSetAttribute(fused_kernel,
                         cudaFuncAttributeMaxDynamicSharedMemorySize, SM_TOTAL);

    prep_kernel<<<289, 128>>>(bincounts, conv1_w, conv1_b, conv2_w, conv2_b,
                              lin1_w, lin1_b, lin2_w, diff);

    dim3 grid(NTILE, B_);
    fused_kernel<<<grid, NTHR, SM_TOTAL>>>(bincounts, lin2_b, baseline, regions_oi);
    combine_kernel<<<(B_ * A_ + 255) / 256, 256>>>();
    gather_kernel<<<(nf + 255) / 256, 256>>>(labels, cell_ix, region_ix,
                                             binixs, out, nf);
}

// round 17
// speedup vs baseline: 1.9139x; 1.1284x over previous
#include <cuda_runtime.h>
#include <cuda_fp16.h>
#include <float.h>
#include <math.h>

#define A_  64
#define B_  256
#define L_  2000
#define TILE 128
#define NTILE 16
#define NTHR 256

typedef unsigned long long u64;
typedef unsigned int u32;

__device__ float g_U[B_ * L_ * A_];
__device__ float g_pmax[B_ * NTILE * A_];
__device__ float g_psum[B_ * NTILE * A_];
__device__ float g_logZ[B_ * A_];

__device__ float2 g_we9[64 * 9];
__device__ float2 g_bep[64];
__device__ float  g_hsb[B_ * 4 * 128];
// fp16 weights, [n][k] rows padded to 136 halves (272B stride)
__device__ __align__(16) u32 g_w2h[128 * 68];
__device__ __align__(16) u32 g_dfh[64 * 68];

// ---------------- shared memory layout (bytes, 16B aligned) -----------------
#define SM_BINC  0         // 576
#define SM_BEP   576       // 512
#define SM_L2B   1088      // 512
#define SM_BM    1600      // 256
#define SM_WE9   1856      // 4608
#define SM_AH    6464      // 34816 (h1/h2 fp16; later ux[64][129] fp32)
#define SM_WB    41280     // 34816 (w2 fp16 during GEMM2; diff fp16 during GEMM3)
#define SM_TOTAL 76096

__device__ __forceinline__ u64 pk2(float x){u64 r;asm("mov.b64 %0,{%1,%1};":"=l"(r):"f"(x));return r;}
__device__ __forceinline__ void fma2(u64&d,u64 a,u64 b){asm("fma.rn.f32x2 %0,%1,%2,%0;":"+l"(d):"l"(a),"l"(b));}
__device__ __forceinline__ float2 up(u64 v){float2 f;asm("mov.b64 {%0,%1},%2;":"=f"(f.x),"=f"(f.y):"l"(v));return f;}
__device__ __forceinline__ u32 stosh(const void*p){u32 a;asm("{ .reg .u64 t; cvta.to.shared.u64 t,%1; cvt.u32.u64 %0,t; }":"=r"(a):"l"(p));return a;}
__device__ __forceinline__ void ldsm4(u32 addr,u32&r0,u32&r1,u32&r2,u32&r3){
    asm volatile("ldmatrix.sync.aligned.m8n8.x4.shared.b16 {%0,%1,%2,%3},[%4];"
        :"=r"(r0),"=r"(r1),"=r"(r2),"=r"(r3):"r"(addr));
}
__device__ __forceinline__ void mma16816(float* c,u32 a0,u32 a1,u32 a2,u32 a3,u32 b0,u32 b1){
    asm volatile("mma.sync.aligned.m16n8k16.row.col.f32.f16.f16.f32 "
        "{%0,%1,%2,%3},{%4,%5,%6,%7},{%8,%9},{%0,%1,%2,%3};"
        :"+f"(c[0]),"+f"(c[1]),"+f"(c[2]),"+f"(c[3])
        :"r"(a0),"r"(a1),"r"(a2),"r"(a3),"r"(b0),"r"(b1));
}

// ===== ONE prep kernel: boundary (blocks 0..255), we9/bep (block 256),
// ===== fp16 weight transposes (blocks 257..288), 128 threads each ==========
__global__ void prep_kernel(const float* __restrict__ binc,
                            const float* __restrict__ w1, const float* __restrict__ b1,
                            const float* __restrict__ w2, const float* __restrict__ b2,
                            const float* __restrict__ l1w, const float* __restrict__ l1b,
                            const float* __restrict__ l2w, const float* __restrict__ diff)
{
    const int blk = blockIdx.x, t = threadIdx.x;

    if (blk < 256) {
        __shared__ float c1L[32][4], c1R[32][4], c2b[4][64], xL[8], xR[8];
        int b = blk;
        const float* x = binc + b * L_;
        if (t < 6)            xL[t]     = x[t];
        if (t >= 8 && t < 14) xR[t - 8] = x[L_ - 6 + t - 8];
        __syncthreads();
        {
            int ic = t >> 2, p = t & 3;
            float aL = b1[ic], aR = b1[ic];
            #pragma unroll
            for (int k = 0; k < 5; k++) {
                float w = w1[ic * 5 + k];
                int qL = p + k - 2; if (qL >= 0) aL += w * xL[qL];
                int qR = p + k;     if (qR < 6)  aR += w * xR[qR];
            }
            c1L[ic][p] = aL; c1R[ic][p] = aR;
        }
        __syncthreads();
        {
            int oc = t & 63, li0 = t >> 6;
            #pragma unroll
            for (int e = 0; e < 2; e++) {
                int li = li0 + 2 * e;
                float acc = b2[oc];
                for (int ic = 0; ic < 32; ic++) {
                    const float* wr = &w2[(oc * 32 + ic) * 5];
                    if (li == 0)      { for (int k = 2; k < 5; k++) acc += wr[k] * c1L[ic][k - 2]; }
                    else if (li == 1) { for (int k = 1; k < 5; k++) acc += wr[k] * c1L[ic][k - 1]; }
                    else if (li == 2) { for (int k = 0; k < 4; k++) acc += wr[k] * c1R[ic][k]; }
                    else              { for (int k = 0; k < 3; k++) acc += wr[k] * c1R[ic][k + 1]; }
                }
                c2b[li][oc] = acc;
            }
        }
        __syncthreads();
        {
            int j = t;
            #pragma unroll
            for (int li = 0; li < 4; li++) {
                float h = l1b[j];
                for (int oc = 0; oc < 64; oc++) h += l1w[j * 64 + oc] * c2b[li][oc];
                g_hsb[b * 512 + li * 128 + j] = fmaxf(h, 0.f);
            }
        }
    } else if (blk == 256) {
        __shared__ float sWC[64 * 9], sbC[64];
        for (int i = t; i < 576; i += 128) {
            int oc = i / 9, tt = i % 9;
            float s = 0.f;
            for (int ic = 0; ic < 32; ic++) {
                int klo = tt - 4 > 0 ? tt - 4 : 0, khi = tt < 4 ? tt : 4;
                for (int k = klo; k <= khi; k++)
                    s += w2[(oc * 32 + ic) * 5 + k] * w1[ic * 5 + (tt - k)];
            }
            sWC[i] = s;
        }
        if (t < 64) {
            float s = b2[t];
            for (int ic = 0; ic < 32; ic++) {
                float ws = 0.f;
                for (int k = 0; k < 5; k++) ws += w2[(t * 32 + ic) * 5 + k];
                s += b1[ic] * ws;
            }
            sbC[t] = s;
        }
        __syncthreads();
        for (int i = t; i < 576; i += 128) {
            int jp = i / 9, tt = i % 9;
            float sx = 0.f, sy = 0.f;
            for (int oc = 0; oc < 64; oc++) {
                float wc = sWC[oc * 9 + tt];
                sx += l1w[(2 * jp) * 64 + oc] * wc;
                sy += l1w[(2 * jp + 1) * 64 + oc] * wc;
            }
            g_we9[i] = make_float2(sx, sy);
        }
        if (t < 64) {
            int jp = t;
            float sx = l1b[2 * jp], sy = l1b[2 * jp + 1];
            for (int oc = 0; oc < 64; oc++) {
                float bc = sbC[oc];
                sx += l1w[(2 * jp) * 64 + oc] * bc;
                sy += l1w[(2 * jp + 1) * 64 + oc] * bc;
            }
            g_bep[jp] = make_float2(sx, sy);
        }
    } else {
        int base = (blk - 257) * 128 + t;
        for (int i = base; i < 128 * 128; i += 32 * 128) {
            int n = i >> 7, k = i & 127;
            ((__half*)g_w2h)[n * 136 + k] = __float2half_rn(l2w[i]);
        }
        for (int i = base; i < 64 * 128; i += 32 * 128) {
            int n = i >> 7, k = i & 127;
            ((__half*)g_dfh)[n * 136 + k] = __float2half_rn(diff[i]);
        }
    }
}

__global__ void __launch_bounds__(NTHR, 2)
fused_kernel(const float* __restrict__ binc_g, const float* __restrict__ l2b_g,
             const float* __restrict__ baseline_g, const int* __restrict__ regions_oi_g)
{
    extern __shared__ char smem[];
    const int t = threadIdx.x, wid = t >> 5, lane = t & 31;
    const int tileIdx = blockIdx.x, b = blockIdx.y;
    const int l0 = tileIdx * TILE;
    const u32 sb = stosh(smem);

    // ---- staging: w2 fp16, we9, bep, l2b, bincounts halo ----
    {
        float4* dh = (float4*)(smem + SM_WB); const float4* shh = (const float4*)g_w2h;
        for (int i = t; i < 2176; i += NTHR) dh[i] = shh[i];
        float4* d = (float4*)(smem + SM_WE9); const float4* s = (const float4*)g_we9;
        for (int i = t; i < 288; i += NTHR) d[i] = s[i];
    }
    if (t < 32)  ((float4*)(smem + SM_BEP))[t] = ((const float4*)g_bep)[t];
    if (t < 128) ((float*)(smem + SM_L2B))[t]  = l2b_g[t];
    if (t < 136) {
        int l = l0 - 4 + t;
        ((float*)(smem + SM_BINC))[t] = (l >= 0 && l < L_) ? binc_g[b * L_ + l] : 0.f;
    }
    __syncthreads();

    // ---- conv9 -> h1 fp16 [l][k], 272B row stride ----
    {
        const u64* swe = (const u64*)(smem + SM_WE9);
        const u64* sbep = (const u64*)(smem + SM_BEP);
        const float* sbinc = (const float*)(smem + SM_BINC);
        int jp = t & 63, lbq = t >> 6;   // lbq 0..3
        u64 wp[9];
        #pragma unroll
        for (int k = 0; k < 9; k++) wp[k] = swe[jp * 9 + k];
        u64 bini = sbep[jp];
        #pragma unroll
        for (int q = 0; q < 4; q++) {
            int lb = (lbq + 4 * q) * 8;
            u64 acc[8];
            #pragma unroll
            for (int i = 0; i < 8; i++) acc[i] = bini;
            u64 xv[16];
            #pragma unroll
            for (int g = 0; g < 4; g++) {
                float4 v = *(const float4*)&sbinc[lb + g * 4];
                xv[g*4] = pk2(v.x); xv[g*4+1] = pk2(v.y); xv[g*4+2] = pk2(v.z); xv[g*4+3] = pk2(v.w);
            }
            #pragma unroll
            for (int k = 0; k < 9; k++) {
                u64 w = wp[k];
                #pragma unroll
                for (int i = 0; i < 8; i++) fma2(acc[i], xv[i + k], w);
            }
            #pragma unroll
            for (int i = 0; i < 8; i++) {
                float2 v = up(acc[i]);
                __half2 h2v = __floats2half2_rn(fmaxf(v.x, 0.f), fmaxf(v.y, 0.f));
                *(u32*)(smem + SM_AH + (u32)((lb + i) * 272 + jp * 4)) = *(u32*)&h2v;
            }
        }
    }
    if (tileIdx == 0 || tileIdx == NTILE - 1) {
        __syncthreads();
        int li = t >> 7, k = t & 127;
        int l  = (tileIdx == 0) ? li : (78 + li);
        int hb = (tileIdx == 0) ? li : (2 + li);
        float v = g_hsb[b * 512 + hb * 128 + k];
        *(__half*)(smem + SM_AH + l * 272 + k * 2) = __float2half_rn(v);
    }
    __syncthreads();

    // ---- warp tiling: 4 warps along M (32 rows), 2 along N ----
    const int m0 = (wid & 3) * 32;
    const u32 aoff = (u32)((m0 + (lane & 15)) * 272 + (lane >> 4) * 16);
    const u32 brow = (u32)(((lane >> 4) * 8 + (lane & 7)) * 272 + ((lane >> 3) & 1) * 16);

    // ==== GEMM2: h2 = relu(A @ w2^T + b2), single-pass fp16 ====
    {
        const int n0 = (wid >> 2) * 64;
        float C[2][8][4];
        #pragma unroll
        for (int mt = 0; mt < 2; mt++)
            #pragma unroll
            for (int nt = 0; nt < 8; nt++)
                #pragma unroll
                for (int j = 0; j < 4; j++) C[mt][nt][j] = 0.f;
        u32 Ab = sb + SM_AH + aoff;
        u32 Bb = sb + SM_WB + (u32)(n0 * 272) + brow;
        #pragma unroll 2
        for (int ks = 0; ks < 8; ks++) {
            u32 kb = (u32)(ks * 32);
            u32 ah[2][4], bt[8][2];
            ldsm4(Ab + kb,            ah[0][0], ah[0][1], ah[0][2], ah[0][3]);
            ldsm4(Ab + 16 * 272 + kb, ah[1][0], ah[1][1], ah[1][2], ah[1][3]);
            #pragma unroll
            for (int q = 0; q < 4; q++) {
                u32 r0, r1, r2, r3;
                ldsm4(Bb + (u32)(q * 16 * 272) + kb, r0, r1, r2, r3);
                bt[2*q][0] = r0; bt[2*q][1] = r1; bt[2*q+1][0] = r2; bt[2*q+1][1] = r3;
            }
            #pragma unroll
            for (int mt = 0; mt < 2; mt++)
                #pragma unroll
                for (int nt = 0; nt < 8; nt++)
                    mma16816(C[mt][nt], ah[mt][0], ah[mt][1], ah[mt][2], ah[mt][3], bt[nt][0], bt[nt][1]);
        }
        __syncthreads();   // all warps done reading h1 + w2

        // epilogue2: bias+relu -> h2 fp16 [l][j]
        const float* sl2b = (const float*)(smem + SM_L2B);
        #pragma unroll
        for (int mt = 0; mt < 2; mt++) {
            int la = m0 + mt * 16 + (lane >> 2);
            int lb2 = la + 8;
            #pragma unroll
            for (int nt = 0; nt < 8; nt++) {
                float* c = C[mt][nt];
                int j = n0 + nt * 8 + (lane & 3) * 2;
                float bj0 = sl2b[j], bj1 = sl2b[j + 1];
                __half2 h0 = __floats2half2_rn(fmaxf(c[0] + bj0, 0.f), fmaxf(c[1] + bj1, 0.f));
                __half2 h1 = __floats2half2_rn(fmaxf(c[2] + bj0, 0.f), fmaxf(c[3] + bj1, 0.f));
                *(u32*)(smem + SM_AH + la  * 272 + j * 2) = *(u32*)&h0;
                *(u32*)(smem + SM_AH + lb2 * 272 + j * 2) = *(u32*)&h1;
            }
        }
    }
    {
        float4* eh = (float4*)(smem + SM_WB); const float4* gh = (const float4*)g_dfh;
        for (int i = t; i < 1088; i += NTHR) eh[i] = gh[i];
    }
    __syncthreads();

    // ==== GEMM3: u = h2 @ diff^T + baseline, M=128 N=64, single-pass ====
    float C3[2][4][4];
    #pragma unroll
    for (int mt = 0; mt < 2; mt++)
        #pragma unroll
        for (int nt = 0; nt < 4; nt++)
            #pragma unroll
            for (int j = 0; j < 4; j++) C3[mt][nt][j] = 0.f;
    const int n03 = (wid >> 2) * 32;
    {
        u32 Ab = sb + SM_AH + aoff;
        u32 Bb = sb + SM_WB + (u32)(n03 * 272) + brow;
        #pragma unroll 2
        for (int ks = 0; ks < 8; ks++) {
            u32 kb = (u32)(ks * 32);
            u32 ah[2][4], bt[4][2];
            ldsm4(Ab + kb,            ah[0][0], ah[0][1], ah[0][2], ah[0][3]);
            ldsm4(Ab + 16 * 272 + kb, ah[1][0], ah[1][1], ah[1][2], ah[1][3]);
            #pragma unroll
            for (int q = 0; q < 2; q++) {
                u32 r0, r1, r2, r3;
                ldsm4(Bb + (u32)(q * 16 * 272) + kb, r0, r1, r2, r3);
                bt[2*q][0] = r0; bt[2*q][1] = r1; bt[2*q+1][0] = r2; bt[2*q+1][1] = r3;
            }
            #pragma unroll
            for (int mt = 0; mt < 2; mt++)
                #pragma unroll
                for (int nt = 0; nt < 4; nt++)
                    mma16816(C3[mt][nt], ah[mt][0], ah[mt][1], ah[mt][2], ah[mt][3], bt[nt][0], bt[nt][1]);
        }
    }
    __syncthreads();   // done reading h2 -> AH region reusable as ux

    // epilogue3: u = C3 + baseline; write g_U; LSE partials via ux transpose
    {
        const int rgn = regions_oi_g[b];
        float* ux = (float*)(smem + SM_AH);   // [64][129] fp32
        float* bmv = (float*)(smem + SM_BM);
        #pragma unroll
        for (int mt = 0; mt < 2; mt++) {
            int lr0 = m0 + mt * 16 + (lane >> 2);
            int lr1 = lr0 + 8;
            int gl0 = l0 + lr0, gl1 = l0 + lr1;
            bool v0 = gl0 < L_, v1 = gl1 < L_;
            float base0 = v0 ? baseline_g[rgn * L_ + gl0] : 0.f;
            float base1 = v1 ? baseline_g[rgn * L_ + gl1] : 0.f;
            #pragma unroll
            for (int nt = 0; nt < 4; nt++) {
                float* c = C3[mt][nt];
                int a = n03 + nt * 8 + (lane & 3) * 2;
                float u0 = v0 ? c[0] + base0 : -FLT_MAX;
                float u1 = v0 ? c[1] + base0 : -FLT_MAX;
                float u2 = v1 ? c[2] + base1 : -FLT_MAX;
                float u3 = v1 ? c[3] + base1 : -FLT_MAX;
                if (v0) *(float2*)&g_U[((size_t)(b * L_ + gl0)) * A_ + a] = make_float2(u0, u1);
                if (v1) *(float2*)&g_U[((size_t)(b * L_ + gl1)) * A_ + a] = make_float2(u2, u3);
                ux[a * 129 + lr0] = u0; ux[(a + 1) * 129 + lr0] = u1;
                ux[a * 129 + lr1] = u2; ux[(a + 1) * 129 + lr1] = u3;
            }
        }
        __syncthreads();
        // parallel LSE: 4 threads per a-row, 32 elems each
        const int row = t >> 2, sub = t & 3;
        const float* rp = &ux[row * 129 + sub * 32];
        float m = -FLT_MAX;
        #pragma unroll
        for (int i = 0; i < 32; i++) m = fmaxf(m, rp[i]);
        #pragma unroll
        for (int off = 2; off > 0; off >>= 1)
            m = fmaxf(m, __shfl_down_sync(0xffffffffu, m, off, 4));
        if (sub == 0) bmv[row] = m;
        __syncthreads();
        float mrow = bmv[row];
        float s = 0.f;
        #pragma unroll
        for (int i = 0; i < 32; i++) s += __expf(rp[i] - mrow);
        #pragma unroll
        for (int off = 2; off > 0; off >>= 1)
            s += __shfl_down_sync(0xffffffffu, s, off, 4);
        if (sub == 0) {
            g_pmax[(b * NTILE + tileIdx) * A_ + row] = mrow;
            g_psum[(b * NTILE + tileIdx) * A_ + row] = s;
        }
    }
}

__global__ void combine_kernel()
{
    int id = blockIdx.x * blockDim.x + threadIdx.x;
    if (id >= B_ * A_) return;
    int b = id >> 6, a = id & 63;
    float m = -FLT_MAX;
    #pragma unroll
    for (int q = 0; q < NTILE; q++)
        m = fmaxf(m, g_pmax[(b * NTILE + q) * A_ + a]);
    float s = 0.f;
    #pragma unroll
    for (int q = 0; q < NTILE; q++)
        s += g_psum[(b * NTILE + q) * A_ + a] * __expf(g_pmax[(b * NTILE + q) * A_ + a] - m);
    g_logZ[b * A_ + a] = m + logf(s);
}

__global__ void gather_kernel(const int* __restrict__ labels, const int* __restrict__ cell_ix,
                              const int* __restrict__ region_ix, const int* __restrict__ binixs,
                              float* __restrict__ out, int nf)
{
    int f = blockIdx.x * blockDim.x + threadIdx.x;
    if (f >= nf) return;
    int a = labels[cell_ix[f]];
    int b = region_ix[f];
    int l = binixs[f];
    out[f] = g_U[(size_t)(b * L_ + l) * A_ + a] - g_logZ[b * A_ + a] + 5.545177444479562f;
}

extern "C" void kernel_launch(void* const* d_in, const int* in_sizes, int n_in,
                              void* d_out, int out_size)
{
    const float* bincounts  = (const float*)d_in[0];
    const float* conv1_w    = (const float*)d_in[1];
    const float* conv1_b    = (const float*)d_in[2];
    const float* conv2_w    = (const float*)d_in[3];
    const float* conv2_b    = (const float*)d_in[4];
    const float* lin1_w     = (const float*)d_in[5];
    const float* lin1_b     = (const float*)d_in[6];
    const float* lin2_w     = (const float*)d_in[7];
    const float* lin2_b     = (const float*)d_in[8];
    const float* baseline   = (const float*)d_in[9];
    const float* diff       = (const float*)d_in[10];
    const int*   regions_oi = (const int*)d_in[11];
    const int*   labels     = (const int*)d_in[12];
    const int*   cell_ix    = (const int*)d_in[13];
    const int*   region_ix  = (const int*)d_in[14];
    const int*   binixs     = (const int*)d_in[15];
    float* out = (float*)d_out;
    int nf = in_sizes[13];

    cudaFuncSetAttribute(fused_kernel,
                         cudaFuncAttributeMaxDynamicSharedMemorySize, SM_TOTAL);

    prep_kernel<<<289, 128>>>(bincounts, conv1_w, conv1_b, conv2_w, conv2_b,
                              lin1_w, lin1_b, lin2_w, diff);

    dim3 grid(NTILE, B_);
    fused_kernel<<<grid, NTHR, SM_TOTAL>>>(bincounts, lin2_b, baseline, regions_oi);
    combine_kernel<<<(B_ * A_ + 255) / 256, 256>>>();
    gather_kernel<<<(nf + 255) / 256, 256>>>(labels, cell_ix, region_ix,
                                             binixs, out, nf);
}